// round 8
// baseline (speedup 1.0000x reference)
#include <cuda_runtime.h>
#include <math.h>

#define NN   8192
#define DIMK 512

// Scratch (static __device__ — allocation-free per harness rules)
__device__ float g_n1[NN * DIMK];
__device__ float g_n2[NN * DIMK];
__device__ float g_S[(size_t)NN * NN];

// ---------------------------------------------------------------------------
// Bit-exact replica of XLA's f32 tanh as actually codegen'd (FMA-contracted
// Horner chains; separate roundings for x2, x*P and the division).
// ---------------------------------------------------------------------------
__device__ __forceinline__ float tanh_xla(float x)
{
    const float ax = fabsf(x);
    const float xc = fminf(fmaxf(x, -9.0f), 9.0f);
    const float x2 = __fmul_rn(xc, xc);

    float p = -2.76076847742355e-16f;
    p = __fmaf_rn(p, x2,  2.00018790482477e-13f);
    p = __fmaf_rn(p, x2, -8.60467152213735e-11f);
    p = __fmaf_rn(p, x2,  5.12229709037114e-08f);
    p = __fmaf_rn(p, x2,  1.48572235717979e-05f);
    p = __fmaf_rn(p, x2,  6.37261928875436e-04f);
    p = __fmaf_rn(p, x2,  4.89352455891786e-03f);
    const float num = __fmul_rn(xc, p);

    float q = 1.19825839466702e-06f;
    q = __fmaf_rn(q, x2, 1.18534705686654e-04f);
    q = __fmaf_rn(q, x2, 2.26843463243900e-03f);
    q = __fmaf_rn(q, x2, 4.89352518554385e-03f);

    const float r = __fdiv_rn(num, q);
    return (ax < 0.0004f) ? x : r;
}

// packed f32x2 FMA: each half is an independent rn-rounded FMA (bitwise equal
// to scalar fmaf); accumulate in place.
__device__ __forceinline__ void fma2(unsigned long long& acc,
                                     unsigned long long a2,
                                     unsigned long long b2)
{
    asm("fma.rn.f32x2 %0, %1, %2, %0;" : "+l"(acc) : "l"(a2), "l"(b2));
}

// ---------------------------------------------------------------------------
// PHASE 1: SGEMM NT x2 with gather + tanh epilogue (R6-measured best).
// A pre-duplicated in smem as (a,a) pairs; no min-blocks cap (small grid,
// occupancy irrelevant at 256 CTAs).
// ---------------------------------------------------------------------------
__global__ void __launch_bounds__(256)
sgemm_nt_x2_epi(const float* __restrict__ A, const float* __restrict__ B,
                const float* __restrict__ bias, const int* __restrict__ idx,
                float* __restrict__ C, int M, int N, int K)
{
    constexpr int BM = 128, BN = 128, BK = 16;
    __shared__ float2 As2[2][BK][BM];
    __shared__ float  Bs [2][BK][BN];

    const int tid = threadIdx.x;
    const int bx = blockIdx.x, by = blockIdx.y;

    const int lr = tid >> 2;
    const int lc = (tid & 3) << 2;

    int ar0 = idx[by * BM + lr];
    int ar1 = idx[by * BM + lr + 64];
    const float* Ap0 = A + (size_t)ar0 * K + lc;
    const float* Ap1 = A + (size_t)ar1 * K + lc;
    const float* Bp0 = B + (size_t)(bx * BN + lr) * K + lc;
    const float* Bp1 = B + (size_t)(bx * BN + lr + 64) * K + lc;

    const int rm = (tid >> 4) << 3;
    const int rn = (tid & 15) << 3;

    unsigned long long acc2[8][4];
    #pragma unroll
    for (int i = 0; i < 8; ++i)
        #pragma unroll
        for (int j = 0; j < 4; ++j) acc2[i][j] = 0ull;

    float4 pa0, pa1, pb0, pb1;

    pa0 = *reinterpret_cast<const float4*>(Ap0);
    pa1 = *reinterpret_cast<const float4*>(Ap1);
    pb0 = *reinterpret_cast<const float4*>(Bp0);
    pb1 = *reinterpret_cast<const float4*>(Bp1);
    {
        As2[0][lc + 0][lr] = make_float2(pa0.x, pa0.x);
        As2[0][lc + 1][lr] = make_float2(pa0.y, pa0.y);
        As2[0][lc + 2][lr] = make_float2(pa0.z, pa0.z);
        As2[0][lc + 3][lr] = make_float2(pa0.w, pa0.w);
        As2[0][lc + 0][lr + 64] = make_float2(pa1.x, pa1.x);
        As2[0][lc + 1][lr + 64] = make_float2(pa1.y, pa1.y);
        As2[0][lc + 2][lr + 64] = make_float2(pa1.z, pa1.z);
        As2[0][lc + 3][lr + 64] = make_float2(pa1.w, pa1.w);
        Bs[0][lc + 0][lr] = pb0.x; Bs[0][lc + 1][lr] = pb0.y;
        Bs[0][lc + 2][lr] = pb0.z; Bs[0][lc + 3][lr] = pb0.w;
        Bs[0][lc + 0][lr + 64] = pb1.x; Bs[0][lc + 1][lr + 64] = pb1.y;
        Bs[0][lc + 2][lr + 64] = pb1.z; Bs[0][lc + 3][lr + 64] = pb1.w;
    }
    __syncthreads();

    int read = 0;
    for (int kt = BK; kt <= K; kt += BK) {
        const bool more = (kt < K);
        if (more) {
            pa0 = *reinterpret_cast<const float4*>(Ap0 + kt);
            pa1 = *reinterpret_cast<const float4*>(Ap1 + kt);
            pb0 = *reinterpret_cast<const float4*>(Bp0 + kt);
            pb1 = *reinterpret_cast<const float4*>(Bp1 + kt);
        }
        #pragma unroll
        for (int kk = 0; kk < BK; ++kk) {
            unsigned long long ra2[8], rb2[4];
            *reinterpret_cast<float4*>(&ra2[0]) = *reinterpret_cast<const float4*>(&As2[read][kk][rm]);
            *reinterpret_cast<float4*>(&ra2[2]) = *reinterpret_cast<const float4*>(&As2[read][kk][rm + 2]);
            *reinterpret_cast<float4*>(&ra2[4]) = *reinterpret_cast<const float4*>(&As2[read][kk][rm + 4]);
            *reinterpret_cast<float4*>(&ra2[6]) = *reinterpret_cast<const float4*>(&As2[read][kk][rm + 6]);
            *reinterpret_cast<float4*>(&rb2[0]) = *reinterpret_cast<const float4*>(&Bs[read][kk][rn]);
            *reinterpret_cast<float4*>(&rb2[2]) = *reinterpret_cast<const float4*>(&Bs[read][kk][rn + 4]);

            #pragma unroll
            for (int i = 0; i < 8; ++i)
                #pragma unroll
                for (int j = 0; j < 4; ++j)
                    fma2(acc2[i][j], ra2[i], rb2[j]);
        }
        if (more) {
            const int w = read ^ 1;
            As2[w][lc + 0][lr] = make_float2(pa0.x, pa0.x);
            As2[w][lc + 1][lr] = make_float2(pa0.y, pa0.y);
            As2[w][lc + 2][lr] = make_float2(pa0.z, pa0.z);
            As2[w][lc + 3][lr] = make_float2(pa0.w, pa0.w);
            As2[w][lc + 0][lr + 64] = make_float2(pa1.x, pa1.x);
            As2[w][lc + 1][lr + 64] = make_float2(pa1.y, pa1.y);
            As2[w][lc + 2][lr + 64] = make_float2(pa1.z, pa1.z);
            As2[w][lc + 3][lr + 64] = make_float2(pa1.w, pa1.w);
            Bs[w][lc + 0][lr] = pb0.x; Bs[w][lc + 1][lr] = pb0.y;
            Bs[w][lc + 2][lr] = pb0.z; Bs[w][lc + 3][lr] = pb0.w;
            Bs[w][lc + 0][lr + 64] = pb1.x; Bs[w][lc + 1][lr + 64] = pb1.y;
            Bs[w][lc + 2][lr + 64] = pb1.z; Bs[w][lc + 3][lr + 64] = pb1.w;
            __syncthreads();
            read = w;
        }
    }

    #pragma unroll
    for (int i = 0; i < 8; ++i) {
        const size_t row = (size_t)(by * BM + rm + i);
        float v[8];
        #pragma unroll
        for (int j = 0; j < 4; ++j) {
            const float2 u = *reinterpret_cast<const float2*>(&acc2[i][j]);
            v[2 * j]     = u.x;
            v[2 * j + 1] = u.y;
        }
        #pragma unroll
        for (int j = 0; j < 8; ++j) {
            float x = __fadd_rn(v[j], bias[bx * BN + rn + j]);
            x = __fmul_rn(3.0f, x);
            v[j] = tanh_xla(x);
        }
        float4* cp = reinterpret_cast<float4*>(C + row * (size_t)N + bx * BN + rn);
        cp[0] = make_float4(v[0], v[1], v[2], v[3]);
        cp[1] = make_float4(v[4], v[5], v[6], v[7]);
    }
}

// ---------------------------------------------------------------------------
// PHASE 2: SGEMM NT x2, plain, WITH minBlocks=2 (the untested quadrant:
// good FFMA2 codegen from pre-dup smem + 2 CTAs/SM for latency hiding).
// ---------------------------------------------------------------------------
__global__ void __launch_bounds__(256, 2)
sgemm_nt_x2_p2(const float* __restrict__ A, const float* __restrict__ B,
               float* __restrict__ C, int M, int N, int K)
{
    constexpr int BM = 128, BN = 128, BK = 16;
    __shared__ float2 As2[2][BK][BM];
    __shared__ float  Bs [2][BK][BN];

    const int tid = threadIdx.x;
    const int bx = blockIdx.x, by = blockIdx.y;

    const int lr = tid >> 2;
    const int lc = (tid & 3) << 2;

    const float* Ap0 = A + (size_t)(by * BM + lr) * K + lc;
    const float* Ap1 = A + (size_t)(by * BM + lr + 64) * K + lc;
    const float* Bp0 = B + (size_t)(bx * BN + lr) * K + lc;
    const float* Bp1 = B + (size_t)(bx * BN + lr + 64) * K + lc;

    const int rm = (tid >> 4) << 3;
    const int rn = (tid & 15) << 3;

    unsigned long long acc2[8][4];
    #pragma unroll
    for (int i = 0; i < 8; ++i)
        #pragma unroll
        for (int j = 0; j < 4; ++j) acc2[i][j] = 0ull;

    float4 pa0, pa1, pb0, pb1;

    pa0 = *reinterpret_cast<const float4*>(Ap0);
    pa1 = *reinterpret_cast<const float4*>(Ap1);
    pb0 = *reinterpret_cast<const float4*>(Bp0);
    pb1 = *reinterpret_cast<const float4*>(Bp1);
    {
        As2[0][lc + 0][lr] = make_float2(pa0.x, pa0.x);
        As2[0][lc + 1][lr] = make_float2(pa0.y, pa0.y);
        As2[0][lc + 2][lr] = make_float2(pa0.z, pa0.z);
        As2[0][lc + 3][lr] = make_float2(pa0.w, pa0.w);
        As2[0][lc + 0][lr + 64] = make_float2(pa1.x, pa1.x);
        As2[0][lc + 1][lr + 64] = make_float2(pa1.y, pa1.y);
        As2[0][lc + 2][lr + 64] = make_float2(pa1.z, pa1.z);
        As2[0][lc + 3][lr + 64] = make_float2(pa1.w, pa1.w);
        Bs[0][lc + 0][lr] = pb0.x; Bs[0][lc + 1][lr] = pb0.y;
        Bs[0][lc + 2][lr] = pb0.z; Bs[0][lc + 3][lr] = pb0.w;
        Bs[0][lc + 0][lr + 64] = pb1.x; Bs[0][lc + 1][lr + 64] = pb1.y;
        Bs[0][lc + 2][lr + 64] = pb1.z; Bs[0][lc + 3][lr + 64] = pb1.w;
    }
    __syncthreads();

    int read = 0;
    for (int kt = BK; kt <= K; kt += BK) {
        const bool more = (kt < K);
        if (more) {
            pa0 = *reinterpret_cast<const float4*>(Ap0 + kt);
            pa1 = *reinterpret_cast<const float4*>(Ap1 + kt);
            pb0 = *reinterpret_cast<const float4*>(Bp0 + kt);
            pb1 = *reinterpret_cast<const float4*>(Bp1 + kt);
        }
        #pragma unroll
        for (int kk = 0; kk < BK; ++kk) {
            unsigned long long ra2[8], rb2[4];
            *reinterpret_cast<float4*>(&ra2[0]) = *reinterpret_cast<const float4*>(&As2[read][kk][rm]);
            *reinterpret_cast<float4*>(&ra2[2]) = *reinterpret_cast<const float4*>(&As2[read][kk][rm + 2]);
            *reinterpret_cast<float4*>(&ra2[4]) = *reinterpret_cast<const float4*>(&As2[read][kk][rm + 4]);
            *reinterpret_cast<float4*>(&ra2[6]) = *reinterpret_cast<const float4*>(&As2[read][kk][rm + 6]);
            *reinterpret_cast<float4*>(&rb2[0]) = *reinterpret_cast<const float4*>(&Bs[read][kk][rn]);
            *reinterpret_cast<float4*>(&rb2[2]) = *reinterpret_cast<const float4*>(&Bs[read][kk][rn + 4]);

            #pragma unroll
            for (int i = 0; i < 8; ++i)
                #pragma unroll
                for (int j = 0; j < 4; ++j)
                    fma2(acc2[i][j], ra2[i], rb2[j]);
        }
        if (more) {
            const int w = read ^ 1;
            As2[w][lc + 0][lr] = make_float2(pa0.x, pa0.x);
            As2[w][lc + 1][lr] = make_float2(pa0.y, pa0.y);
            As2[w][lc + 2][lr] = make_float2(pa0.z, pa0.z);
            As2[w][lc + 3][lr] = make_float2(pa0.w, pa0.w);
            As2[w][lc + 0][lr + 64] = make_float2(pa1.x, pa1.x);
            As2[w][lc + 1][lr + 64] = make_float2(pa1.y, pa1.y);
            As2[w][lc + 2][lr + 64] = make_float2(pa1.z, pa1.z);
            As2[w][lc + 3][lr + 64] = make_float2(pa1.w, pa1.w);
            Bs[w][lc + 0][lr] = pb0.x; Bs[w][lc + 1][lr] = pb0.y;
            Bs[w][lc + 2][lr] = pb0.z; Bs[w][lc + 3][lr] = pb0.w;
            Bs[w][lc + 0][lr + 64] = pb1.x; Bs[w][lc + 1][lr + 64] = pb1.y;
            Bs[w][lc + 2][lr + 64] = pb1.z; Bs[w][lc + 3][lr + 64] = pb1.w;
            __syncthreads();
            read = w;
        }
    }

    #pragma unroll
    for (int i = 0; i < 8; ++i) {
        const size_t row = (size_t)(by * BM + rm + i);
        float4* cp = reinterpret_cast<float4*>(C + row * (size_t)N + bx * BN + rn);
        const float2 u0 = *reinterpret_cast<const float2*>(&acc2[i][0]);
        const float2 u1 = *reinterpret_cast<const float2*>(&acc2[i][1]);
        const float2 u2 = *reinterpret_cast<const float2*>(&acc2[i][2]);
        const float2 u3 = *reinterpret_cast<const float2*>(&acc2[i][3]);
        cp[0] = make_float4(u0.x, u0.y, u1.x, u1.y);
        cp[1] = make_float4(u2.x, u2.y, u3.x, u3.y);
    }
}

// ---------------------------------------------------------------------------
// In-place antisymmetrize + tanh: adj = tanh(3*(S - S^T)), tile-pair per CTA.
// ---------------------------------------------------------------------------
__global__ void __launch_bounds__(512)
antisym_tanh(float* __restrict__ S, int N)
{
    const int I = blockIdx.y, J = blockIdx.x;
    if (J < I) return;

    __shared__ float t1[64][65];
    __shared__ float t2[64][65];

    const int c  = threadIdx.x & 63;
    const int r0 = (threadIdx.x >> 6) << 3;

    const size_t base1 = (size_t)(I * 64) * N + (size_t)(J * 64);
    const size_t base2 = (size_t)(J * 64) * N + (size_t)(I * 64);

    #pragma unroll
    for (int e = 0; e < 8; ++e) {
        const int r = r0 + e;
        t1[r][c] = S[base1 + (size_t)r * N + c];
        t2[r][c] = S[base2 + (size_t)r * N + c];
    }
    __syncthreads();

    float v[8];
    #pragma unroll
    for (int e = 0; e < 8; ++e) {
        const int r = r0 + e;
        const float a = __fadd_rn(t1[r][c], -t2[c][r]);
        v[e] = tanh_xla(__fmul_rn(3.0f, a));
    }
    __syncthreads();

    #pragma unroll
    for (int e = 0; e < 8; ++e) {
        const int r = r0 + e;
        S[base1 + (size_t)r * N + c] = v[e];
        t2[c][r] = -v[e];
    }
    __syncthreads();

    if (I != J) {
        #pragma unroll
        for (int e = 0; e < 8; ++e) {
            const int r = r0 + e;
            S[base2 + (size_t)r * N + c] = t2[r][c];
        }
    }
}

// ---------------------------------------------------------------------------
// Per-row exact top-k mask with jax.lax.top_k tie semantics.
// ---------------------------------------------------------------------------
#define EQ_CAP 256

__global__ void __launch_bounds__(256)
topk_mask(const float* __restrict__ adj, const float* __restrict__ noise,
          const int* __restrict__ kptr, float* __restrict__ out, int N, int kdef)
{
    __shared__ float sadj[NN];
    __shared__ int cnt[32];
    __shared__ int eq_idx[EQ_CAP];
    __shared__ int eq_n;
    __shared__ int gt_n;

    const int row = blockIdx.x;
    const int tid = threadIdx.x;
    const float* ar = adj   + (size_t)row * N;
    const float* nr = noise + (size_t)row * N;

    unsigned pbits[32];
    #pragma unroll
    for (int e = 0; e < 32; ++e) {
        const int j = tid + (e << 8);
        const float a = ar[j];
        const float p = fabsf(__fmaf_rn(0.01f, nr[j], a));
        sadj[j]  = a;
        pbits[e] = __float_as_uint(p);
    }
    if (tid < 32) cnt[tid] = 0;
    if (tid == 0) { eq_n = 0; gt_n = 0; }
    __syncthreads();

    const int k = kptr ? *kptr : kdef;
    unsigned prefix = 0;
    int kk = k;
    for (int b = 30; b >= 0; --b) {
        const unsigned cand = prefix | (1u << b);
        const unsigned hm   = ~((1u << b) - 1u);
        int c = 0;
        #pragma unroll
        for (int e = 0; e < 32; ++e) c += ((pbits[e] & hm) == cand);
        #pragma unroll
        for (int o = 16; o > 0; o >>= 1) c += __shfl_xor_sync(0xffffffffu, c, o);
        if ((tid & 31) == 0) atomicAdd(&cnt[b], c);
        __syncthreads();
        const int tot = cnt[b];
        if (tot >= kk) prefix = cand; else kk -= tot;
    }

    const unsigned T = prefix;

    {
        int cgt = 0;
        #pragma unroll
        for (int e = 0; e < 32; ++e) cgt += (pbits[e] > T);
        #pragma unroll
        for (int o = 16; o > 0; o >>= 1) cgt += __shfl_xor_sync(0xffffffffu, cgt, o);
        if ((tid & 31) == 0) atomicAdd(&gt_n, cgt);

        #pragma unroll
        for (int e = 0; e < 32; ++e) {
            if (pbits[e] == T) {
                const int s = atomicAdd(&eq_n, 1);
                if (s < EQ_CAP) eq_idx[s] = tid + (e << 8);
            }
        }
    }
    __syncthreads();

    const int need = k - gt_n;
    const int en   = (eq_n < EQ_CAP) ? eq_n : EQ_CAP;

    #pragma unroll
    for (int e = 0; e < 32; ++e) {
        const int j = tid + (e << 8);
        bool keep = (pbits[e] > T);
        if (!keep && pbits[e] == T) {
            int r = 0;
            for (int q = 0; q < en; ++q) r += (eq_idx[q] < j);
            keep = (r < need);
        }
        out[(size_t)row * N + j] = keep ? sadj[j] : 0.0f;
    }
}

// ---------------------------------------------------------------------------
// Launcher: inputs in metadata order:
// idx, emb1, emb2, lin1_w, lin1_b, lin2_w, lin2_b, noise, k
// ---------------------------------------------------------------------------
extern "C" void kernel_launch(void* const* d_in, const int* in_sizes, int n_in,
                              void* d_out, int out_size)
{
    const int*   idx   = (const int*)  d_in[0];
    const float* emb1  = (const float*)d_in[1];
    const float* emb2  = (const float*)d_in[2];
    const float* w1    = (const float*)d_in[3];
    const float* b1    = (const float*)d_in[4];
    const float* w2    = (const float*)d_in[5];
    const float* b2    = (const float*)d_in[6];
    const float* noise = (const float*)d_in[7];
    const int*   kptr  = (n_in > 8) ? (const int*)d_in[8] : nullptr;
    float* out = (float*)d_out;

    float *n1, *n2, *S;
    cudaGetSymbolAddress((void**)&n1, g_n1);
    cudaGetSymbolAddress((void**)&n2, g_n2);
    cudaGetSymbolAddress((void**)&S,  g_S);

    // Phase 1 (x2, R6 config): n1/n2 = tanh(3*(emb[idx] @ W^T + b))
    {
        dim3 grid(DIMK / 128, NN / 128);
        sgemm_nt_x2_epi<<<grid, 256>>>(emb1, w1, b1, idx, n1, NN, DIMK, DIMK);
        sgemm_nt_x2_epi<<<grid, 256>>>(emb2, w2, b2, idx, n2, NN, DIMK, DIMK);
    }

    // Phase 2 (x2 + minBlocks=2): S = n1 @ n2^T
    {
        dim3 grid(NN / 128, NN / 128);
        sgemm_nt_x2_p2<<<grid, 256>>>(n1, n2, S, NN, NN, DIMK);
    }

    // Phase 3: adj = tanh(3*(S - S^T)) in place (tile pairs)
    {
        dim3 grid(NN / 64, NN / 64);
        antisym_tanh<<<grid, 512>>>(S, NN);
    }

    // Phase 4: per-row exact top-k mask (jax tie semantics) -> output
    topk_mask<<<NN, 256>>>(S, noise, kptr, out, NN, 64);
}

// round 9
// speedup vs baseline: 1.1538x; 1.1538x over previous
#include <cuda_runtime.h>
#include <math.h>

#define NN   8192
#define DIMK 512

// Scratch (static __device__ — allocation-free per harness rules)
__device__ float g_n1[NN * DIMK];
__device__ float g_n2[NN * DIMK];
__device__ float g_S[(size_t)NN * NN];

// ---------------------------------------------------------------------------
// Bit-exact replica of XLA's f32 tanh as actually codegen'd (FMA-contracted
// Horner chains; separate roundings for x2, x*P and the division).
// ---------------------------------------------------------------------------
__device__ __forceinline__ float tanh_xla(float x)
{
    const float ax = fabsf(x);
    const float xc = fminf(fmaxf(x, -9.0f), 9.0f);
    const float x2 = __fmul_rn(xc, xc);

    float p = -2.76076847742355e-16f;
    p = __fmaf_rn(p, x2,  2.00018790482477e-13f);
    p = __fmaf_rn(p, x2, -8.60467152213735e-11f);
    p = __fmaf_rn(p, x2,  5.12229709037114e-08f);
    p = __fmaf_rn(p, x2,  1.48572235717979e-05f);
    p = __fmaf_rn(p, x2,  6.37261928875436e-04f);
    p = __fmaf_rn(p, x2,  4.89352455891786e-03f);
    const float num = __fmul_rn(xc, p);

    float q = 1.19825839466702e-06f;
    q = __fmaf_rn(q, x2, 1.18534705686654e-04f);
    q = __fmaf_rn(q, x2, 2.26843463243900e-03f);
    q = __fmaf_rn(q, x2, 4.89352518554385e-03f);

    const float r = __fdiv_rn(num, q);
    return (ax < 0.0004f) ? x : r;
}

// packed f32x2 FMA: each half is an independent rn-rounded FMA (bitwise equal
// to scalar fmaf); accumulate in place.
__device__ __forceinline__ void fma2(unsigned long long& acc,
                                     unsigned long long a2,
                                     unsigned long long b2)
{
    asm("fma.rn.f32x2 %0, %1, %2, %0;" : "+l"(acc) : "l"(a2), "l"(b2));
}

// swap the two f32 lanes of a u64 pair
__device__ __forceinline__ unsigned long long swap2(unsigned long long v)
{
    unsigned lo, hi;
    asm("mov.b64 {%0,%1}, %2;" : "=r"(lo), "=r"(hi) : "l"(v));
    unsigned long long r;
    asm("mov.b64 %0, {%1,%2};" : "=l"(r) : "r"(hi), "r"(lo));
    return r;
}

// ---------------------------------------------------------------------------
// PHASE 1: SGEMM NT x2 with gather + tanh epilogue (R6-measured best, ~73us).
// A pre-duplicated in smem as (a,a) pairs; no min-blocks cap.
// ---------------------------------------------------------------------------
__global__ void __launch_bounds__(256)
sgemm_nt_x2_epi(const float* __restrict__ A, const float* __restrict__ B,
                const float* __restrict__ bias, const int* __restrict__ idx,
                float* __restrict__ C, int M, int N, int K)
{
    constexpr int BM = 128, BN = 128, BK = 16;
    __shared__ float2 As2[2][BK][BM];
    __shared__ float  Bs [2][BK][BN];

    const int tid = threadIdx.x;
    const int bx = blockIdx.x, by = blockIdx.y;

    const int lr = tid >> 2;
    const int lc = (tid & 3) << 2;

    int ar0 = idx[by * BM + lr];
    int ar1 = idx[by * BM + lr + 64];
    const float* Ap0 = A + (size_t)ar0 * K + lc;
    const float* Ap1 = A + (size_t)ar1 * K + lc;
    const float* Bp0 = B + (size_t)(bx * BN + lr) * K + lc;
    const float* Bp1 = B + (size_t)(bx * BN + lr + 64) * K + lc;

    const int rm = (tid >> 4) << 3;
    const int rn = (tid & 15) << 3;

    unsigned long long acc2[8][4];
    #pragma unroll
    for (int i = 0; i < 8; ++i)
        #pragma unroll
        for (int j = 0; j < 4; ++j) acc2[i][j] = 0ull;

    float4 pa0, pa1, pb0, pb1;

    pa0 = *reinterpret_cast<const float4*>(Ap0);
    pa1 = *reinterpret_cast<const float4*>(Ap1);
    pb0 = *reinterpret_cast<const float4*>(Bp0);
    pb1 = *reinterpret_cast<const float4*>(Bp1);
    {
        As2[0][lc + 0][lr] = make_float2(pa0.x, pa0.x);
        As2[0][lc + 1][lr] = make_float2(pa0.y, pa0.y);
        As2[0][lc + 2][lr] = make_float2(pa0.z, pa0.z);
        As2[0][lc + 3][lr] = make_float2(pa0.w, pa0.w);
        As2[0][lc + 0][lr + 64] = make_float2(pa1.x, pa1.x);
        As2[0][lc + 1][lr + 64] = make_float2(pa1.y, pa1.y);
        As2[0][lc + 2][lr + 64] = make_float2(pa1.z, pa1.z);
        As2[0][lc + 3][lr + 64] = make_float2(pa1.w, pa1.w);
        Bs[0][lc + 0][lr] = pb0.x; Bs[0][lc + 1][lr] = pb0.y;
        Bs[0][lc + 2][lr] = pb0.z; Bs[0][lc + 3][lr] = pb0.w;
        Bs[0][lc + 0][lr + 64] = pb1.x; Bs[0][lc + 1][lr + 64] = pb1.y;
        Bs[0][lc + 2][lr + 64] = pb1.z; Bs[0][lc + 3][lr + 64] = pb1.w;
    }
    __syncthreads();

    int read = 0;
    for (int kt = BK; kt <= K; kt += BK) {
        const bool more = (kt < K);
        if (more) {
            pa0 = *reinterpret_cast<const float4*>(Ap0 + kt);
            pa1 = *reinterpret_cast<const float4*>(Ap1 + kt);
            pb0 = *reinterpret_cast<const float4*>(Bp0 + kt);
            pb1 = *reinterpret_cast<const float4*>(Bp1 + kt);
        }
        #pragma unroll
        for (int kk = 0; kk < BK; ++kk) {
            unsigned long long ra2[8], rb2[4];
            *reinterpret_cast<float4*>(&ra2[0]) = *reinterpret_cast<const float4*>(&As2[read][kk][rm]);
            *reinterpret_cast<float4*>(&ra2[2]) = *reinterpret_cast<const float4*>(&As2[read][kk][rm + 2]);
            *reinterpret_cast<float4*>(&ra2[4]) = *reinterpret_cast<const float4*>(&As2[read][kk][rm + 4]);
            *reinterpret_cast<float4*>(&ra2[6]) = *reinterpret_cast<const float4*>(&As2[read][kk][rm + 6]);
            *reinterpret_cast<float4*>(&rb2[0]) = *reinterpret_cast<const float4*>(&Bs[read][kk][rn]);
            *reinterpret_cast<float4*>(&rb2[2]) = *reinterpret_cast<const float4*>(&Bs[read][kk][rn + 4]);

            #pragma unroll
            for (int i = 0; i < 8; ++i)
                #pragma unroll
                for (int j = 0; j < 4; ++j)
                    fma2(acc2[i][j], ra2[i], rb2[j]);
        }
        if (more) {
            const int w = read ^ 1;
            As2[w][lc + 0][lr] = make_float2(pa0.x, pa0.x);
            As2[w][lc + 1][lr] = make_float2(pa0.y, pa0.y);
            As2[w][lc + 2][lr] = make_float2(pa0.z, pa0.z);
            As2[w][lc + 3][lr] = make_float2(pa0.w, pa0.w);
            As2[w][lc + 0][lr + 64] = make_float2(pa1.x, pa1.x);
            As2[w][lc + 1][lr + 64] = make_float2(pa1.y, pa1.y);
            As2[w][lc + 2][lr + 64] = make_float2(pa1.z, pa1.z);
            As2[w][lc + 3][lr + 64] = make_float2(pa1.w, pa1.w);
            Bs[w][lc + 0][lr] = pb0.x; Bs[w][lc + 1][lr] = pb0.y;
            Bs[w][lc + 2][lr] = pb0.z; Bs[w][lc + 3][lr] = pb0.w;
            Bs[w][lc + 0][lr + 64] = pb1.x; Bs[w][lc + 1][lr + 64] = pb1.y;
            Bs[w][lc + 2][lr + 64] = pb1.z; Bs[w][lc + 3][lr + 64] = pb1.w;
            __syncthreads();
            read = w;
        }
    }

    #pragma unroll
    for (int i = 0; i < 8; ++i) {
        const size_t row = (size_t)(by * BM + rm + i);
        float v[8];
        #pragma unroll
        for (int j = 0; j < 4; ++j) {
            const float2 u = *reinterpret_cast<const float2*>(&acc2[i][j]);
            v[2 * j]     = u.x;
            v[2 * j + 1] = u.y;
        }
        #pragma unroll
        for (int j = 0; j < 8; ++j) {
            float x = __fadd_rn(v[j], bias[bx * BN + rn + j]);
            x = __fmul_rn(3.0f, x);
            v[j] = tanh_xla(x);
        }
        float4* cp = reinterpret_cast<float4*>(C + row * (size_t)N + bx * BN + rn);
        cp[0] = make_float4(v[0], v[1], v[2], v[3]);
        cp[1] = make_float4(v[4], v[5], v[6], v[7]);
    }
}

// ---------------------------------------------------------------------------
// PHASE 2: diagonal-packed FFMA2 SGEMM NT. Natural (non-duplicated) smem
// operands — same 4x LDS.128 per kk as the scalar kernel (1 B/FMA, smem at
// 50% of crossbar) but half the FMA instructions.
//   accD[s][t] = (C[2s][2t],   C[2s+1][2t+1]) += a2[s] *      b2[t]
//   accX[s][t] = (C[2s][2t+1], C[2s+1][2t]  ) += a2[s] * swap(b2[t])
// 128x128x16 tiles, 256 threads, 8x8 outputs per thread, 2 CTAs/SM.
// ---------------------------------------------------------------------------
__global__ void __launch_bounds__(256, 2)
sgemm_nt_diag(const float* __restrict__ A, const float* __restrict__ B,
              float* __restrict__ C, int M, int N, int K)
{
    constexpr int BM = 128, BN = 128, BK = 16;
    __shared__ float As[2][BK][BM + 4];
    __shared__ float Bs[2][BK][BN + 4];

    const int tid = threadIdx.x;
    const int bx = blockIdx.x, by = blockIdx.y;

    const int lr = tid >> 2;
    const int lc = (tid & 3) << 2;

    const float* Ap0 = A + (size_t)(by * BM + lr) * K + lc;
    const float* Ap1 = A + (size_t)(by * BM + lr + 64) * K + lc;
    const float* Bp0 = B + (size_t)(bx * BN + lr) * K + lc;
    const float* Bp1 = B + (size_t)(bx * BN + lr + 64) * K + lc;

    const int rm = (tid >> 4) << 3;
    const int rn = (tid & 15) << 3;

    unsigned long long accD[4][4], accX[4][4];
    #pragma unroll
    for (int s = 0; s < 4; ++s)
        #pragma unroll
        for (int t = 0; t < 4; ++t) { accD[s][t] = 0ull; accX[s][t] = 0ull; }

    float4 pa0, pa1, pb0, pb1;

    pa0 = *reinterpret_cast<const float4*>(Ap0);
    pa1 = *reinterpret_cast<const float4*>(Ap1);
    pb0 = *reinterpret_cast<const float4*>(Bp0);
    pb1 = *reinterpret_cast<const float4*>(Bp1);
    {
        As[0][lc + 0][lr] = pa0.x; As[0][lc + 1][lr] = pa0.y;
        As[0][lc + 2][lr] = pa0.z; As[0][lc + 3][lr] = pa0.w;
        As[0][lc + 0][lr + 64] = pa1.x; As[0][lc + 1][lr + 64] = pa1.y;
        As[0][lc + 2][lr + 64] = pa1.z; As[0][lc + 3][lr + 64] = pa1.w;
        Bs[0][lc + 0][lr] = pb0.x; Bs[0][lc + 1][lr] = pb0.y;
        Bs[0][lc + 2][lr] = pb0.z; Bs[0][lc + 3][lr] = pb0.w;
        Bs[0][lc + 0][lr + 64] = pb1.x; Bs[0][lc + 1][lr + 64] = pb1.y;
        Bs[0][lc + 2][lr + 64] = pb1.z; Bs[0][lc + 3][lr + 64] = pb1.w;
    }
    __syncthreads();

    int read = 0;
    for (int kt = BK; kt <= K; kt += BK) {
        const bool more = (kt < K);
        if (more) {
            pa0 = *reinterpret_cast<const float4*>(Ap0 + kt);
            pa1 = *reinterpret_cast<const float4*>(Ap1 + kt);
            pb0 = *reinterpret_cast<const float4*>(Bp0 + kt);
            pb1 = *reinterpret_cast<const float4*>(Bp1 + kt);
        }
        #pragma unroll
        for (int kk = 0; kk < BK; ++kk) {
            unsigned long long a2[4], b2[4];
            // natural pairs straight from smem (16B-aligned: rm,rn mult of 8)
            *reinterpret_cast<float4*>(&a2[0]) = *reinterpret_cast<const float4*>(&As[read][kk][rm]);
            *reinterpret_cast<float4*>(&a2[2]) = *reinterpret_cast<const float4*>(&As[read][kk][rm + 4]);
            *reinterpret_cast<float4*>(&b2[0]) = *reinterpret_cast<const float4*>(&Bs[read][kk][rn]);
            *reinterpret_cast<float4*>(&b2[2]) = *reinterpret_cast<const float4*>(&Bs[read][kk][rn + 4]);

            #pragma unroll
            for (int t = 0; t < 4; ++t) {
                const unsigned long long bs = swap2(b2[t]);
                #pragma unroll
                for (int s = 0; s < 4; ++s) {
                    fma2(accD[s][t], a2[s], b2[t]);
                    fma2(accX[s][t], a2[s], bs);
                }
            }
        }
        if (more) {
            const int w = read ^ 1;
            As[w][lc + 0][lr] = pa0.x; As[w][lc + 1][lr] = pa0.y;
            As[w][lc + 2][lr] = pa0.z; As[w][lc + 3][lr] = pa0.w;
            As[w][lc + 0][lr + 64] = pa1.x; As[w][lc + 1][lr + 64] = pa1.y;
            As[w][lc + 2][lr + 64] = pa1.z; As[w][lc + 3][lr + 64] = pa1.w;
            Bs[w][lc + 0][lr] = pb0.x; Bs[w][lc + 1][lr] = pb0.y;
            Bs[w][lc + 2][lr] = pb0.z; Bs[w][lc + 3][lr] = pb0.w;
            Bs[w][lc + 0][lr + 64] = pb1.x; Bs[w][lc + 1][lr + 64] = pb1.y;
            Bs[w][lc + 2][lr + 64] = pb1.z; Bs[w][lc + 3][lr + 64] = pb1.w;
            __syncthreads();
            read = w;
        }
    }

    // epilogue: unpack diagonal pairs
    #pragma unroll
    for (int i = 0; i < 8; ++i) {
        const int s = i >> 1;
        const size_t row = (size_t)(by * BM + rm + i);
        float v[8];
        if ((i & 1) == 0) {
            #pragma unroll
            for (int t = 0; t < 4; ++t) {
                v[2 * t]     = reinterpret_cast<const float2*>(&accD[s][t])->x;
                v[2 * t + 1] = reinterpret_cast<const float2*>(&accX[s][t])->x;
            }
        } else {
            #pragma unroll
            for (int t = 0; t < 4; ++t) {
                v[2 * t]     = reinterpret_cast<const float2*>(&accX[s][t])->y;
                v[2 * t + 1] = reinterpret_cast<const float2*>(&accD[s][t])->y;
            }
        }
        float4* cp = reinterpret_cast<float4*>(C + row * (size_t)N + bx * BN + rn);
        cp[0] = make_float4(v[0], v[1], v[2], v[3]);
        cp[1] = make_float4(v[4], v[5], v[6], v[7]);
    }
}

// ---------------------------------------------------------------------------
// In-place antisymmetrize + tanh: adj = tanh(3*(S - S^T)), tile-pair per CTA.
// ---------------------------------------------------------------------------
__global__ void __launch_bounds__(512)
antisym_tanh(float* __restrict__ S, int N)
{
    const int I = blockIdx.y, J = blockIdx.x;
    if (J < I) return;

    __shared__ float t1[64][65];
    __shared__ float t2[64][65];

    const int c  = threadIdx.x & 63;
    const int r0 = (threadIdx.x >> 6) << 3;

    const size_t base1 = (size_t)(I * 64) * N + (size_t)(J * 64);
    const size_t base2 = (size_t)(J * 64) * N + (size_t)(I * 64);

    #pragma unroll
    for (int e = 0; e < 8; ++e) {
        const int r = r0 + e;
        t1[r][c] = S[base1 + (size_t)r * N + c];
        t2[r][c] = S[base2 + (size_t)r * N + c];
    }
    __syncthreads();

    float v[8];
    #pragma unroll
    for (int e = 0; e < 8; ++e) {
        const int r = r0 + e;
        const float a = __fadd_rn(t1[r][c], -t2[c][r]);
        v[e] = tanh_xla(__fmul_rn(3.0f, a));
    }
    __syncthreads();

    #pragma unroll
    for (int e = 0; e < 8; ++e) {
        const int r = r0 + e;
        S[base1 + (size_t)r * N + c] = v[e];
        t2[c][r] = -v[e];
    }
    __syncthreads();

    if (I != J) {
        #pragma unroll
        for (int e = 0; e < 8; ++e) {
            const int r = r0 + e;
            S[base2 + (size_t)r * N + c] = t2[r][c];
        }
    }
}

// ---------------------------------------------------------------------------
// Per-row exact top-k mask with jax.lax.top_k tie semantics.
// ---------------------------------------------------------------------------
#define EQ_CAP 256

__global__ void __launch_bounds__(256)
topk_mask(const float* __restrict__ adj, const float* __restrict__ noise,
          const int* __restrict__ kptr, float* __restrict__ out, int N, int kdef)
{
    __shared__ float sadj[NN];
    __shared__ int cnt[32];
    __shared__ int eq_idx[EQ_CAP];
    __shared__ int eq_n;
    __shared__ int gt_n;

    const int row = blockIdx.x;
    const int tid = threadIdx.x;
    const float* ar = adj   + (size_t)row * N;
    const float* nr = noise + (size_t)row * N;

    unsigned pbits[32];
    #pragma unroll
    for (int e = 0; e < 32; ++e) {
        const int j = tid + (e << 8);
        const float a = ar[j];
        const float p = fabsf(__fmaf_rn(0.01f, nr[j], a));
        sadj[j]  = a;
        pbits[e] = __float_as_uint(p);
    }
    if (tid < 32) cnt[tid] = 0;
    if (tid == 0) { eq_n = 0; gt_n = 0; }
    __syncthreads();

    const int k = kptr ? *kptr : kdef;
    unsigned prefix = 0;
    int kk = k;
    for (int b = 30; b >= 0; --b) {
        const unsigned cand = prefix | (1u << b);
        const unsigned hm   = ~((1u << b) - 1u);
        int c = 0;
        #pragma unroll
        for (int e = 0; e < 32; ++e) c += ((pbits[e] & hm) == cand);
        #pragma unroll
        for (int o = 16; o > 0; o >>= 1) c += __shfl_xor_sync(0xffffffffu, c, o);
        if ((tid & 31) == 0) atomicAdd(&cnt[b], c);
        __syncthreads();
        const int tot = cnt[b];
        if (tot >= kk) prefix = cand; else kk -= tot;
    }

    const unsigned T = prefix;

    {
        int cgt = 0;
        #pragma unroll
        for (int e = 0; e < 32; ++e) cgt += (pbits[e] > T);
        #pragma unroll
        for (int o = 16; o > 0; o >>= 1) cgt += __shfl_xor_sync(0xffffffffu, cgt, o);
        if ((tid & 31) == 0) atomicAdd(&gt_n, cgt);

        #pragma unroll
        for (int e = 0; e < 32; ++e) {
            if (pbits[e] == T) {
                const int s = atomicAdd(&eq_n, 1);
                if (s < EQ_CAP) eq_idx[s] = tid + (e << 8);
            }
        }
    }
    __syncthreads();

    const int need = k - gt_n;
    const int en   = (eq_n < EQ_CAP) ? eq_n : EQ_CAP;

    #pragma unroll
    for (int e = 0; e < 32; ++e) {
        const int j = tid + (e << 8);
        bool keep = (pbits[e] > T);
        if (!keep && pbits[e] == T) {
            int r = 0;
            for (int q = 0; q < en; ++q) r += (eq_idx[q] < j);
            keep = (r < need);
        }
        out[(size_t)row * N + j] = keep ? sadj[j] : 0.0f;
    }
}

// ---------------------------------------------------------------------------
// Launcher: inputs in metadata order:
// idx, emb1, emb2, lin1_w, lin1_b, lin2_w, lin2_b, noise, k
// ---------------------------------------------------------------------------
extern "C" void kernel_launch(void* const* d_in, const int* in_sizes, int n_in,
                              void* d_out, int out_size)
{
    const int*   idx   = (const int*)  d_in[0];
    const float* emb1  = (const float*)d_in[1];
    const float* emb2  = (const float*)d_in[2];
    const float* w1    = (const float*)d_in[3];
    const float* b1    = (const float*)d_in[4];
    const float* w2    = (const float*)d_in[5];
    const float* b2    = (const float*)d_in[6];
    const float* noise = (const float*)d_in[7];
    const int*   kptr  = (n_in > 8) ? (const int*)d_in[8] : nullptr;
    float* out = (float*)d_out;

    float *n1, *n2, *S;
    cudaGetSymbolAddress((void**)&n1, g_n1);
    cudaGetSymbolAddress((void**)&n2, g_n2);
    cudaGetSymbolAddress((void**)&S,  g_S);

    // Phase 1 (x2, R6 config): n1/n2 = tanh(3*(emb[idx] @ W^T + b))
    {
        dim3 grid(DIMK / 128, NN / 128);
        sgemm_nt_x2_epi<<<grid, 256>>>(emb1, w1, b1, idx, n1, NN, DIMK, DIMK);
        sgemm_nt_x2_epi<<<grid, 256>>>(emb2, w2, b2, idx, n2, NN, DIMK, DIMK);
    }

    // Phase 2 (diagonal FFMA2, scalar-equal smem traffic): S = n1 @ n2^T
    {
        dim3 grid(NN / 128, NN / 128);
        sgemm_nt_diag<<<grid, 256>>>(n1, n2, S, NN, NN, DIMK);
    }

    // Phase 3: adj = tanh(3*(S - S^T)) in place (tile pairs)
    {
        dim3 grid(NN / 64, NN / 64);
        antisym_tanh<<<grid, 512>>>(S, NN);
    }

    // Phase 4: per-row exact top-k mask (jax tie semantics) -> output
    topk_mask<<<NN, 256>>>(S, noise, kptr, out, NN, 64);
}

// round 10
// speedup vs baseline: 1.2749x; 1.1050x over previous
#include <cuda_runtime.h>
#include <math.h>

#define NN   8192
#define DIMK 512

// Scratch (static __device__ — allocation-free per harness rules)
__device__ float g_n1[NN * DIMK];
__device__ float g_n2[NN * DIMK];
__device__ float g_S[(size_t)NN * NN];

// ---------------------------------------------------------------------------
// Bit-exact replica of XLA's f32 tanh as actually codegen'd (FMA-contracted
// Horner chains; separate roundings for x2, x*P and the division).
// Note: bitwise ODD — tanh_xla(-x) == -tanh_xla(x) — relied on by the
// antisymmetric mirror write.
// ---------------------------------------------------------------------------
__device__ __forceinline__ float tanh_xla(float x)
{
    const float ax = fabsf(x);
    const float xc = fminf(fmaxf(x, -9.0f), 9.0f);
    const float x2 = __fmul_rn(xc, xc);

    float p = -2.76076847742355e-16f;
    p = __fmaf_rn(p, x2,  2.00018790482477e-13f);
    p = __fmaf_rn(p, x2, -8.60467152213735e-11f);
    p = __fmaf_rn(p, x2,  5.12229709037114e-08f);
    p = __fmaf_rn(p, x2,  1.48572235717979e-05f);
    p = __fmaf_rn(p, x2,  6.37261928875436e-04f);
    p = __fmaf_rn(p, x2,  4.89352455891786e-03f);
    const float num = __fmul_rn(xc, p);

    float q = 1.19825839466702e-06f;
    q = __fmaf_rn(q, x2, 1.18534705686654e-04f);
    q = __fmaf_rn(q, x2, 2.26843463243900e-03f);
    q = __fmaf_rn(q, x2, 4.89352518554385e-03f);

    const float r = __fdiv_rn(num, q);
    return (ax < 0.0004f) ? x : r;
}

// packed f32x2 FMA: each half is an independent rn-rounded FMA (bitwise equal
// to scalar fmaf); accumulate in place.
__device__ __forceinline__ void fma2(unsigned long long& acc,
                                     unsigned long long a2,
                                     unsigned long long b2)
{
    asm("fma.rn.f32x2 %0, %1, %2, %0;" : "+l"(acc) : "l"(a2), "l"(b2));
}

// ---------------------------------------------------------------------------
// PHASE 1: SGEMM NT x2 with gather + tanh epilogue (R6-measured best).
// A pre-duplicated in smem as (a,a) pairs; no min-blocks cap.
// ---------------------------------------------------------------------------
__global__ void __launch_bounds__(256)
sgemm_nt_x2_epi(const float* __restrict__ A, const float* __restrict__ B,
                const float* __restrict__ bias, const int* __restrict__ idx,
                float* __restrict__ C, int M, int N, int K)
{
    constexpr int BM = 128, BN = 128, BK = 16;
    __shared__ float2 As2[2][BK][BM];
    __shared__ float  Bs [2][BK][BN];

    const int tid = threadIdx.x;
    const int bx = blockIdx.x, by = blockIdx.y;

    const int lr = tid >> 2;
    const int lc = (tid & 3) << 2;

    int ar0 = idx[by * BM + lr];
    int ar1 = idx[by * BM + lr + 64];
    const float* Ap0 = A + (size_t)ar0 * K + lc;
    const float* Ap1 = A + (size_t)ar1 * K + lc;
    const float* Bp0 = B + (size_t)(bx * BN + lr) * K + lc;
    const float* Bp1 = B + (size_t)(bx * BN + lr + 64) * K + lc;

    const int rm = (tid >> 4) << 3;
    const int rn = (tid & 15) << 3;

    unsigned long long acc2[8][4];
    #pragma unroll
    for (int i = 0; i < 8; ++i)
        #pragma unroll
        for (int j = 0; j < 4; ++j) acc2[i][j] = 0ull;

    float4 pa0, pa1, pb0, pb1;

    pa0 = *reinterpret_cast<const float4*>(Ap0);
    pa1 = *reinterpret_cast<const float4*>(Ap1);
    pb0 = *reinterpret_cast<const float4*>(Bp0);
    pb1 = *reinterpret_cast<const float4*>(Bp1);
    {
        As2[0][lc + 0][lr] = make_float2(pa0.x, pa0.x);
        As2[0][lc + 1][lr] = make_float2(pa0.y, pa0.y);
        As2[0][lc + 2][lr] = make_float2(pa0.z, pa0.z);
        As2[0][lc + 3][lr] = make_float2(pa0.w, pa0.w);
        As2[0][lc + 0][lr + 64] = make_float2(pa1.x, pa1.x);
        As2[0][lc + 1][lr + 64] = make_float2(pa1.y, pa1.y);
        As2[0][lc + 2][lr + 64] = make_float2(pa1.z, pa1.z);
        As2[0][lc + 3][lr + 64] = make_float2(pa1.w, pa1.w);
        Bs[0][lc + 0][lr] = pb0.x; Bs[0][lc + 1][lr] = pb0.y;
        Bs[0][lc + 2][lr] = pb0.z; Bs[0][lc + 3][lr] = pb0.w;
        Bs[0][lc + 0][lr + 64] = pb1.x; Bs[0][lc + 1][lr + 64] = pb1.y;
        Bs[0][lc + 2][lr + 64] = pb1.z; Bs[0][lc + 3][lr + 64] = pb1.w;
    }
    __syncthreads();

    int read = 0;
    for (int kt = BK; kt <= K; kt += BK) {
        const bool more = (kt < K);
        if (more) {
            pa0 = *reinterpret_cast<const float4*>(Ap0 + kt);
            pa1 = *reinterpret_cast<const float4*>(Ap1 + kt);
            pb0 = *reinterpret_cast<const float4*>(Bp0 + kt);
            pb1 = *reinterpret_cast<const float4*>(Bp1 + kt);
        }
        #pragma unroll
        for (int kk = 0; kk < BK; ++kk) {
            unsigned long long ra2[8], rb2[4];
            *reinterpret_cast<float4*>(&ra2[0]) = *reinterpret_cast<const float4*>(&As2[read][kk][rm]);
            *reinterpret_cast<float4*>(&ra2[2]) = *reinterpret_cast<const float4*>(&As2[read][kk][rm + 2]);
            *reinterpret_cast<float4*>(&ra2[4]) = *reinterpret_cast<const float4*>(&As2[read][kk][rm + 4]);
            *reinterpret_cast<float4*>(&ra2[6]) = *reinterpret_cast<const float4*>(&As2[read][kk][rm + 6]);
            *reinterpret_cast<float4*>(&rb2[0]) = *reinterpret_cast<const float4*>(&Bs[read][kk][rn]);
            *reinterpret_cast<float4*>(&rb2[2]) = *reinterpret_cast<const float4*>(&Bs[read][kk][rn + 4]);

            #pragma unroll
            for (int i = 0; i < 8; ++i)
                #pragma unroll
                for (int j = 0; j < 4; ++j)
                    fma2(acc2[i][j], ra2[i], rb2[j]);
        }
        if (more) {
            const int w = read ^ 1;
            As2[w][lc + 0][lr] = make_float2(pa0.x, pa0.x);
            As2[w][lc + 1][lr] = make_float2(pa0.y, pa0.y);
            As2[w][lc + 2][lr] = make_float2(pa0.z, pa0.z);
            As2[w][lc + 3][lr] = make_float2(pa0.w, pa0.w);
            As2[w][lc + 0][lr + 64] = make_float2(pa1.x, pa1.x);
            As2[w][lc + 1][lr + 64] = make_float2(pa1.y, pa1.y);
            As2[w][lc + 2][lr + 64] = make_float2(pa1.z, pa1.z);
            As2[w][lc + 3][lr + 64] = make_float2(pa1.w, pa1.w);
            Bs[w][lc + 0][lr] = pb0.x; Bs[w][lc + 1][lr] = pb0.y;
            Bs[w][lc + 2][lr] = pb0.z; Bs[w][lc + 3][lr] = pb0.w;
            Bs[w][lc + 0][lr + 64] = pb1.x; Bs[w][lc + 1][lr + 64] = pb1.y;
            Bs[w][lc + 2][lr + 64] = pb1.z; Bs[w][lc + 3][lr + 64] = pb1.w;
            __syncthreads();
            read = w;
        }
    }

    #pragma unroll
    for (int i = 0; i < 8; ++i) {
        const size_t row = (size_t)(by * BM + rm + i);
        float v[8];
        #pragma unroll
        for (int j = 0; j < 4; ++j) {
            const float2 u = *reinterpret_cast<const float2*>(&acc2[i][j]);
            v[2 * j]     = u.x;
            v[2 * j + 1] = u.y;
        }
        #pragma unroll
        for (int j = 0; j < 8; ++j) {
            float x = __fadd_rn(v[j], bias[bx * BN + rn + j]);
            x = __fmul_rn(3.0f, x);
            v[j] = tanh_xla(x);
        }
        float4* cp = reinterpret_cast<float4*>(C + row * (size_t)N + bx * BN + rn);
        cp[0] = make_float4(v[0], v[1], v[2], v[3]);
        cp[1] = make_float4(v[4], v[5], v[6], v[7]);
    }
}

// ---------------------------------------------------------------------------
// PHASE 2+3 FUSED: adj = tanh(3*(n1@n2^T - n2@n1^T)) written directly.
// CTA (I,J) with J>=I computes BOTH S1 = n1_I@n2_J^T and S2 = n2_I@n1_J^T
// (each a k-sequential scalar-FMA chain, bitwise-matching the reference
// matmuls), combines adj_IJ = tanh(3*(S1-S2)), writes tile (I,J) coalesced
// and tile (J,I) = -adj_IJ^T via register transpose (scattered float4 — same
// instruction count, 32B DRAM sectors).
// 128x128 tile, 512 threads, 8x4 outputs/thread x 2 accumulators.
// ---------------------------------------------------------------------------
__global__ void __launch_bounds__(512, 1)
antisym_gemm(const float* __restrict__ n1, const float* __restrict__ n2,
             float* __restrict__ adj, int N, int K)
{
    const int I = blockIdx.y, J = blockIdx.x;
    if (J < I) return;

    constexpr int BK = 16;
    __shared__ float As1[2][BK][132];   // n1 rows of tile I (A side)
    __shared__ float As2[2][BK][132];   // n2 rows of tile I
    __shared__ float Bs1[2][BK][132];   // n2 rows of tile J (B side)
    __shared__ float Bs2[2][BK][132];   // n1 rows of tile J

    const int tid = threadIdx.x;

    // ---- loader mapping: 4 warps-groups of 128 threads, one smem tile each
    const int which = tid >> 7;          // 0..3
    const int t4 = tid & 127;
    const int lr = t4 >> 2;              // 0..31
    const int lc = (t4 & 3) << 2;        // 0,4,8,12

    const float* src;
    int rowbase;
    if (which == 0)      { src = n1; rowbase = I * 128; }
    else if (which == 1) { src = n2; rowbase = I * 128; }
    else if (which == 2) { src = n2; rowbase = J * 128; }
    else                 { src = n1; rowbase = J * 128; }
    const float* lp = src + (size_t)(rowbase + lr) * K + lc;

    float (*dst)[BK][132] = (which == 0) ? As1 : (which == 1) ? As2
                          : (which == 2) ? Bs1 : Bs2;

    // ---- compute mapping: 8 rows x 4 cols per thread
    const int rm = (tid >> 5) << 3;      // 0..120
    const int rn = (tid & 31) << 2;      // 0..124

    float acc1[8][4], acc2[8][4];
    #pragma unroll
    for (int i = 0; i < 8; ++i)
        #pragma unroll
        for (int j = 0; j < 4; ++j) { acc1[i][j] = 0.0f; acc2[i][j] = 0.0f; }

    float4 pf[4];

    // prologue: k-tile 0
    #pragma unroll
    for (int r = 0; r < 4; ++r)
        pf[r] = *reinterpret_cast<const float4*>(lp + (size_t)(r * 32) * K);
    #pragma unroll
    for (int r = 0; r < 4; ++r) {
        const int row = lr + r * 32;
        dst[0][lc + 0][row] = pf[r].x;
        dst[0][lc + 1][row] = pf[r].y;
        dst[0][lc + 2][row] = pf[r].z;
        dst[0][lc + 3][row] = pf[r].w;
    }
    __syncthreads();

    int read = 0;
    for (int kt = BK; kt <= K; kt += BK) {
        const bool more = (kt < K);
        if (more) {
            #pragma unroll
            for (int r = 0; r < 4; ++r)
                pf[r] = *reinterpret_cast<const float4*>(lp + (size_t)(r * 32) * K + kt);
        }
        #pragma unroll
        for (int kk = 0; kk < BK; ++kk) {
            float ra1[8], ra2[8], rb1[4], rb2[4];
            *reinterpret_cast<float4*>(&ra1[0]) = *reinterpret_cast<const float4*>(&As1[read][kk][rm]);
            *reinterpret_cast<float4*>(&ra1[4]) = *reinterpret_cast<const float4*>(&As1[read][kk][rm + 4]);
            *reinterpret_cast<float4*>(&ra2[0]) = *reinterpret_cast<const float4*>(&As2[read][kk][rm]);
            *reinterpret_cast<float4*>(&ra2[4]) = *reinterpret_cast<const float4*>(&As2[read][kk][rm + 4]);
            *reinterpret_cast<float4*>(&rb1[0]) = *reinterpret_cast<const float4*>(&Bs1[read][kk][rn]);
            *reinterpret_cast<float4*>(&rb2[0]) = *reinterpret_cast<const float4*>(&Bs2[read][kk][rn]);

            #pragma unroll
            for (int i = 0; i < 8; ++i)
                #pragma unroll
                for (int j = 0; j < 4; ++j)
                    acc1[i][j] = fmaf(ra1[i], rb1[j], acc1[i][j]);
            #pragma unroll
            for (int i = 0; i < 8; ++i)
                #pragma unroll
                for (int j = 0; j < 4; ++j)
                    acc2[i][j] = fmaf(ra2[i], rb2[j], acc2[i][j]);
        }
        if (more) {
            const int w = read ^ 1;
            #pragma unroll
            for (int r = 0; r < 4; ++r) {
                const int row = lr + r * 32;
                dst[w][lc + 0][row] = pf[r].x;
                dst[w][lc + 1][row] = pf[r].y;
                dst[w][lc + 2][row] = pf[r].z;
                dst[w][lc + 3][row] = pf[r].w;
            }
            __syncthreads();
            read = w;
        }
    }

    // epilogue: adj = tanh(3*(S1 - S2)); write (I,J) and mirror (J,I)
    float v[8][4];
    #pragma unroll
    for (int i = 0; i < 8; ++i)
        #pragma unroll
        for (int j = 0; j < 4; ++j) {
            const float a = __fadd_rn(acc1[i][j], -acc2[i][j]);
            v[i][j] = tanh_xla(__fmul_rn(3.0f, a));
        }

    #pragma unroll
    for (int i = 0; i < 8; ++i) {
        float4* cp = reinterpret_cast<float4*>(
            adj + (size_t)(I * 128 + rm + i) * N + J * 128 + rn);
        *cp = make_float4(v[i][0], v[i][1], v[i][2], v[i][3]);
    }

    if (I != J) {
        #pragma unroll
        for (int j = 0; j < 4; ++j) {
            float4* mp = reinterpret_cast<float4*>(
                adj + (size_t)(J * 128 + rn + j) * N + I * 128 + rm);
            mp[0] = make_float4(-v[0][j], -v[1][j], -v[2][j], -v[3][j]);
            mp[1] = make_float4(-v[4][j], -v[5][j], -v[6][j], -v[7][j]);
        }
    }
}

// ---------------------------------------------------------------------------
// Per-row exact top-k mask with jax.lax.top_k tie semantics.
// ---------------------------------------------------------------------------
#define EQ_CAP 256

__global__ void __launch_bounds__(256)
topk_mask(const float* __restrict__ adj, const float* __restrict__ noise,
          const int* __restrict__ kptr, float* __restrict__ out, int N, int kdef)
{
    __shared__ float sadj[NN];
    __shared__ int cnt[32];
    __shared__ int eq_idx[EQ_CAP];
    __shared__ int eq_n;
    __shared__ int gt_n;

    const int row = blockIdx.x;
    const int tid = threadIdx.x;
    const float* ar = adj   + (size_t)row * N;
    const float* nr = noise + (size_t)row * N;

    unsigned pbits[32];
    #pragma unroll
    for (int e = 0; e < 32; ++e) {
        const int j = tid + (e << 8);
        const float a = ar[j];
        const float p = fabsf(__fmaf_rn(0.01f, nr[j], a));
        sadj[j]  = a;
        pbits[e] = __float_as_uint(p);
    }
    if (tid < 32) cnt[tid] = 0;
    if (tid == 0) { eq_n = 0; gt_n = 0; }
    __syncthreads();

    const int k = kptr ? *kptr : kdef;
    unsigned prefix = 0;
    int kk = k;
    for (int b = 30; b >= 0; --b) {
        const unsigned cand = prefix | (1u << b);
        const unsigned hm   = ~((1u << b) - 1u);
        int c = 0;
        #pragma unroll
        for (int e = 0; e < 32; ++e) c += ((pbits[e] & hm) == cand);
        #pragma unroll
        for (int o = 16; o > 0; o >>= 1) c += __shfl_xor_sync(0xffffffffu, c, o);
        if ((tid & 31) == 0) atomicAdd(&cnt[b], c);
        __syncthreads();
        const int tot = cnt[b];
        if (tot >= kk) prefix = cand; else kk -= tot;
    }

    const unsigned T = prefix;

    {
        int cgt = 0;
        #pragma unroll
        for (int e = 0; e < 32; ++e) cgt += (pbits[e] > T);
        #pragma unroll
        for (int o = 16; o > 0; o >>= 1) cgt += __shfl_xor_sync(0xffffffffu, cgt, o);
        if ((tid & 31) == 0) atomicAdd(&gt_n, cgt);

        #pragma unroll
        for (int e = 0; e < 32; ++e) {
            if (pbits[e] == T) {
                const int s = atomicAdd(&eq_n, 1);
                if (s < EQ_CAP) eq_idx[s] = tid + (e << 8);
            }
        }
    }
    __syncthreads();

    const int need = k - gt_n;
    const int en   = (eq_n < EQ_CAP) ? eq_n : EQ_CAP;

    #pragma unroll
    for (int e = 0; e < 32; ++e) {
        const int j = tid + (e << 8);
        bool keep = (pbits[e] > T);
        if (!keep && pbits[e] == T) {
            int r = 0;
            for (int q = 0; q < en; ++q) r += (eq_idx[q] < j);
            keep = (r < need);
        }
        out[(size_t)row * N + j] = keep ? sadj[j] : 0.0f;
    }
}

// ---------------------------------------------------------------------------
// Launcher: inputs in metadata order:
// idx, emb1, emb2, lin1_w, lin1_b, lin2_w, lin2_b, noise, k
// ---------------------------------------------------------------------------
extern "C" void kernel_launch(void* const* d_in, const int* in_sizes, int n_in,
                              void* d_out, int out_size)
{
    const int*   idx   = (const int*)  d_in[0];
    const float* emb1  = (const float*)d_in[1];
    const float* emb2  = (const float*)d_in[2];
    const float* w1    = (const float*)d_in[3];
    const float* b1    = (const float*)d_in[4];
    const float* w2    = (const float*)d_in[5];
    const float* b2    = (const float*)d_in[6];
    const float* noise = (const float*)d_in[7];
    const int*   kptr  = (n_in > 8) ? (const int*)d_in[8] : nullptr;
    float* out = (float*)d_out;

    float *n1, *n2, *S;
    cudaGetSymbolAddress((void**)&n1, g_n1);
    cudaGetSymbolAddress((void**)&n2, g_n2);
    cudaGetSymbolAddress((void**)&S,  g_S);

    // Phase 1 (x2): n1/n2 = tanh(3*(emb[idx] @ W^T + b))
    {
        dim3 grid(DIMK / 128, NN / 128);
        sgemm_nt_x2_epi<<<grid, 256>>>(emb1, w1, b1, idx, n1, NN, DIMK, DIMK);
        sgemm_nt_x2_epi<<<grid, 256>>>(emb2, w2, b2, idx, n2, NN, DIMK, DIMK);
    }

    // Phase 2+3 fused: adj = tanh(3*(n1@n2^T - n2@n1^T)) directly into S
    {
        dim3 grid(NN / 128, NN / 128);   // upper triangle works, rest exit
        antisym_gemm<<<grid, 512>>>(n1, n2, S, NN, DIMK);
    }

    // Phase 4: per-row exact top-k mask (jax tie semantics) -> output
    topk_mask<<<NN, 256>>>(S, noise, kptr, out, NN, 64);
}

// round 11
// speedup vs baseline: 1.2900x; 1.0118x over previous
#include <cuda_runtime.h>
#include <math.h>

#define NN   8192
#define DIMK 512

// Scratch (static __device__ — allocation-free per harness rules)
__device__ float g_n1[NN * DIMK];
__device__ float g_n2[NN * DIMK];
__device__ float g_S[(size_t)NN * NN];

// ---------------------------------------------------------------------------
// Bit-exact replica of XLA's f32 tanh as actually codegen'd (FMA-contracted
// Horner chains; separate roundings for x2, x*P and the division).
// Bitwise ODD — tanh_xla(-x) == -tanh_xla(x) — relied on by the mirror write.
// ---------------------------------------------------------------------------
__device__ __forceinline__ float tanh_xla(float x)
{
    const float ax = fabsf(x);
    const float xc = fminf(fmaxf(x, -9.0f), 9.0f);
    const float x2 = __fmul_rn(xc, xc);

    float p = -2.76076847742355e-16f;
    p = __fmaf_rn(p, x2,  2.00018790482477e-13f);
    p = __fmaf_rn(p, x2, -8.60467152213735e-11f);
    p = __fmaf_rn(p, x2,  5.12229709037114e-08f);
    p = __fmaf_rn(p, x2,  1.48572235717979e-05f);
    p = __fmaf_rn(p, x2,  6.37261928875436e-04f);
    p = __fmaf_rn(p, x2,  4.89352455891786e-03f);
    const float num = __fmul_rn(xc, p);

    float q = 1.19825839466702e-06f;
    q = __fmaf_rn(q, x2, 1.18534705686654e-04f);
    q = __fmaf_rn(q, x2, 2.26843463243900e-03f);
    q = __fmaf_rn(q, x2, 4.89352518554385e-03f);

    const float r = __fdiv_rn(num, q);
    return (ax < 0.0004f) ? x : r;
}

// packed f32x2 FMA: each half is an independent rn-rounded FMA (bitwise equal
// to scalar fmaf); accumulate in place.
__device__ __forceinline__ void fma2(unsigned long long& acc,
                                     unsigned long long a2,
                                     unsigned long long b2)
{
    asm("fma.rn.f32x2 %0, %1, %2, %0;" : "+l"(acc) : "l"(a2), "l"(b2));
}

// ---------------------------------------------------------------------------
// PHASE 1: SGEMM NT x2 with gather + tanh epilogue (R6-measured best).
// ---------------------------------------------------------------------------
__global__ void __launch_bounds__(256)
sgemm_nt_x2_epi(const float* __restrict__ A, const float* __restrict__ B,
                const float* __restrict__ bias, const int* __restrict__ idx,
                float* __restrict__ C, int M, int N, int K)
{
    constexpr int BM = 128, BN = 128, BK = 16;
    __shared__ float2 As2[2][BK][BM];
    __shared__ float  Bs [2][BK][BN];

    const int tid = threadIdx.x;
    const int bx = blockIdx.x, by = blockIdx.y;

    const int lr = tid >> 2;
    const int lc = (tid & 3) << 2;

    int ar0 = idx[by * BM + lr];
    int ar1 = idx[by * BM + lr + 64];
    const float* Ap0 = A + (size_t)ar0 * K + lc;
    const float* Ap1 = A + (size_t)ar1 * K + lc;
    const float* Bp0 = B + (size_t)(bx * BN + lr) * K + lc;
    const float* Bp1 = B + (size_t)(bx * BN + lr + 64) * K + lc;

    const int rm = (tid >> 4) << 3;
    const int rn = (tid & 15) << 3;

    unsigned long long acc2[8][4];
    #pragma unroll
    for (int i = 0; i < 8; ++i)
        #pragma unroll
        for (int j = 0; j < 4; ++j) acc2[i][j] = 0ull;

    float4 pa0, pa1, pb0, pb1;

    pa0 = *reinterpret_cast<const float4*>(Ap0);
    pa1 = *reinterpret_cast<const float4*>(Ap1);
    pb0 = *reinterpret_cast<const float4*>(Bp0);
    pb1 = *reinterpret_cast<const float4*>(Bp1);
    {
        As2[0][lc + 0][lr] = make_float2(pa0.x, pa0.x);
        As2[0][lc + 1][lr] = make_float2(pa0.y, pa0.y);
        As2[0][lc + 2][lr] = make_float2(pa0.z, pa0.z);
        As2[0][lc + 3][lr] = make_float2(pa0.w, pa0.w);
        As2[0][lc + 0][lr + 64] = make_float2(pa1.x, pa1.x);
        As2[0][lc + 1][lr + 64] = make_float2(pa1.y, pa1.y);
        As2[0][lc + 2][lr + 64] = make_float2(pa1.z, pa1.z);
        As2[0][lc + 3][lr + 64] = make_float2(pa1.w, pa1.w);
        Bs[0][lc + 0][lr] = pb0.x; Bs[0][lc + 1][lr] = pb0.y;
        Bs[0][lc + 2][lr] = pb0.z; Bs[0][lc + 3][lr] = pb0.w;
        Bs[0][lc + 0][lr + 64] = pb1.x; Bs[0][lc + 1][lr + 64] = pb1.y;
        Bs[0][lc + 2][lr + 64] = pb1.z; Bs[0][lc + 3][lr + 64] = pb1.w;
    }
    __syncthreads();

    int read = 0;
    for (int kt = BK; kt <= K; kt += BK) {
        const bool more = (kt < K);
        if (more) {
            pa0 = *reinterpret_cast<const float4*>(Ap0 + kt);
            pa1 = *reinterpret_cast<const float4*>(Ap1 + kt);
            pb0 = *reinterpret_cast<const float4*>(Bp0 + kt);
            pb1 = *reinterpret_cast<const float4*>(Bp1 + kt);
        }
        #pragma unroll
        for (int kk = 0; kk < BK; ++kk) {
            unsigned long long ra2[8], rb2[4];
            *reinterpret_cast<float4*>(&ra2[0]) = *reinterpret_cast<const float4*>(&As2[read][kk][rm]);
            *reinterpret_cast<float4*>(&ra2[2]) = *reinterpret_cast<const float4*>(&As2[read][kk][rm + 2]);
            *reinterpret_cast<float4*>(&ra2[4]) = *reinterpret_cast<const float4*>(&As2[read][kk][rm + 4]);
            *reinterpret_cast<float4*>(&ra2[6]) = *reinterpret_cast<const float4*>(&As2[read][kk][rm + 6]);
            *reinterpret_cast<float4*>(&rb2[0]) = *reinterpret_cast<const float4*>(&Bs[read][kk][rn]);
            *reinterpret_cast<float4*>(&rb2[2]) = *reinterpret_cast<const float4*>(&Bs[read][kk][rn + 4]);

            #pragma unroll
            for (int i = 0; i < 8; ++i)
                #pragma unroll
                for (int j = 0; j < 4; ++j)
                    fma2(acc2[i][j], ra2[i], rb2[j]);
        }
        if (more) {
            const int w = read ^ 1;
            As2[w][lc + 0][lr] = make_float2(pa0.x, pa0.x);
            As2[w][lc + 1][lr] = make_float2(pa0.y, pa0.y);
            As2[w][lc + 2][lr] = make_float2(pa0.z, pa0.z);
            As2[w][lc + 3][lr] = make_float2(pa0.w, pa0.w);
            As2[w][lc + 0][lr + 64] = make_float2(pa1.x, pa1.x);
            As2[w][lc + 1][lr + 64] = make_float2(pa1.y, pa1.y);
            As2[w][lc + 2][lr + 64] = make_float2(pa1.z, pa1.z);
            As2[w][lc + 3][lr + 64] = make_float2(pa1.w, pa1.w);
            Bs[w][lc + 0][lr] = pb0.x; Bs[w][lc + 1][lr] = pb0.y;
            Bs[w][lc + 2][lr] = pb0.z; Bs[w][lc + 3][lr] = pb0.w;
            Bs[w][lc + 0][lr + 64] = pb1.x; Bs[w][lc + 1][lr + 64] = pb1.y;
            Bs[w][lc + 2][lr + 64] = pb1.z; Bs[w][lc + 3][lr + 64] = pb1.w;
            __syncthreads();
            read = w;
        }
    }

    #pragma unroll
    for (int i = 0; i < 8; ++i) {
        const size_t row = (size_t)(by * BM + rm + i);
        float v[8];
        #pragma unroll
        for (int j = 0; j < 4; ++j) {
            const float2 u = *reinterpret_cast<const float2*>(&acc2[i][j]);
            v[2 * j]     = u.x;
            v[2 * j + 1] = u.y;
        }
        #pragma unroll
        for (int j = 0; j < 8; ++j) {
            float x = __fadd_rn(v[j], bias[bx * BN + rn + j]);
            x = __fmul_rn(3.0f, x);
            v[j] = tanh_xla(x);
        }
        float4* cp = reinterpret_cast<float4*>(C + row * (size_t)N + bx * BN + rn);
        cp[0] = make_float4(v[0], v[1], v[2], v[3]);
        cp[1] = make_float4(v[4], v[5], v[6], v[7]);
    }
}

// ---------------------------------------------------------------------------
// PHASE 2+3 FUSED: adj = tanh(3*(n1@n2^T - n2@n1^T)) written directly.
// (R10-measured ~1615us — at the scalar FFMA roofline.)
// ---------------------------------------------------------------------------
__global__ void __launch_bounds__(512, 1)
antisym_gemm(const float* __restrict__ n1, const float* __restrict__ n2,
             float* __restrict__ adj, int N, int K)
{
    const int I = blockIdx.y, J = blockIdx.x;
    if (J < I) return;

    constexpr int BK = 16;
    __shared__ float As1[2][BK][132];
    __shared__ float As2[2][BK][132];
    __shared__ float Bs1[2][BK][132];
    __shared__ float Bs2[2][BK][132];

    const int tid = threadIdx.x;

    const int which = tid >> 7;
    const int t4 = tid & 127;
    const int lr = t4 >> 2;
    const int lc = (t4 & 3) << 2;

    const float* src;
    int rowbase;
    if (which == 0)      { src = n1; rowbase = I * 128; }
    else if (which == 1) { src = n2; rowbase = I * 128; }
    else if (which == 2) { src = n2; rowbase = J * 128; }
    else                 { src = n1; rowbase = J * 128; }
    const float* lp = src + (size_t)(rowbase + lr) * K + lc;

    float (*dst)[BK][132] = (which == 0) ? As1 : (which == 1) ? As2
                          : (which == 2) ? Bs1 : Bs2;

    const int rm = (tid >> 5) << 3;
    const int rn = (tid & 31) << 2;

    float acc1[8][4], acc2[8][4];
    #pragma unroll
    for (int i = 0; i < 8; ++i)
        #pragma unroll
        for (int j = 0; j < 4; ++j) { acc1[i][j] = 0.0f; acc2[i][j] = 0.0f; }

    float4 pf[4];

    #pragma unroll
    for (int r = 0; r < 4; ++r)
        pf[r] = *reinterpret_cast<const float4*>(lp + (size_t)(r * 32) * K);
    #pragma unroll
    for (int r = 0; r < 4; ++r) {
        const int row = lr + r * 32;
        dst[0][lc + 0][row] = pf[r].x;
        dst[0][lc + 1][row] = pf[r].y;
        dst[0][lc + 2][row] = pf[r].z;
        dst[0][lc + 3][row] = pf[r].w;
    }
    __syncthreads();

    int read = 0;
    for (int kt = BK; kt <= K; kt += BK) {
        const bool more = (kt < K);
        if (more) {
            #pragma unroll
            for (int r = 0; r < 4; ++r)
                pf[r] = *reinterpret_cast<const float4*>(lp + (size_t)(r * 32) * K + kt);
        }
        #pragma unroll
        for (int kk = 0; kk < BK; ++kk) {
            float ra1[8], ra2[8], rb1[4], rb2[4];
            *reinterpret_cast<float4*>(&ra1[0]) = *reinterpret_cast<const float4*>(&As1[read][kk][rm]);
            *reinterpret_cast<float4*>(&ra1[4]) = *reinterpret_cast<const float4*>(&As1[read][kk][rm + 4]);
            *reinterpret_cast<float4*>(&ra2[0]) = *reinterpret_cast<const float4*>(&As2[read][kk][rm]);
            *reinterpret_cast<float4*>(&ra2[4]) = *reinterpret_cast<const float4*>(&As2[read][kk][rm + 4]);
            *reinterpret_cast<float4*>(&rb1[0]) = *reinterpret_cast<const float4*>(&Bs1[read][kk][rn]);
            *reinterpret_cast<float4*>(&rb2[0]) = *reinterpret_cast<const float4*>(&Bs2[read][kk][rn]);

            #pragma unroll
            for (int i = 0; i < 8; ++i)
                #pragma unroll
                for (int j = 0; j < 4; ++j)
                    acc1[i][j] = fmaf(ra1[i], rb1[j], acc1[i][j]);
            #pragma unroll
            for (int i = 0; i < 8; ++i)
                #pragma unroll
                for (int j = 0; j < 4; ++j)
                    acc2[i][j] = fmaf(ra2[i], rb2[j], acc2[i][j]);
        }
        if (more) {
            const int w = read ^ 1;
            #pragma unroll
            for (int r = 0; r < 4; ++r) {
                const int row = lr + r * 32;
                dst[w][lc + 0][row] = pf[r].x;
                dst[w][lc + 1][row] = pf[r].y;
                dst[w][lc + 2][row] = pf[r].z;
                dst[w][lc + 3][row] = pf[r].w;
            }
            __syncthreads();
            read = w;
        }
    }

    float v[8][4];
    #pragma unroll
    for (int i = 0; i < 8; ++i)
        #pragma unroll
        for (int j = 0; j < 4; ++j) {
            const float a = __fadd_rn(acc1[i][j], -acc2[i][j]);
            v[i][j] = tanh_xla(__fmul_rn(3.0f, a));
        }

    #pragma unroll
    for (int i = 0; i < 8; ++i) {
        float4* cp = reinterpret_cast<float4*>(
            adj + (size_t)(I * 128 + rm + i) * N + J * 128 + rn);
        *cp = make_float4(v[i][0], v[i][1], v[i][2], v[i][3]);
    }

    if (I != J) {
        #pragma unroll
        for (int j = 0; j < 4; ++j) {
            float4* mp = reinterpret_cast<float4*>(
                adj + (size_t)(J * 128 + rn + j) * N + I * 128 + rm);
            mp[0] = make_float4(-v[0][j], -v[1][j], -v[2][j], -v[3][j]);
            mp[1] = make_float4(-v[4][j], -v[5][j], -v[6][j], -v[7][j]);
        }
    }
}

// ---------------------------------------------------------------------------
// PHASE 4: per-row exact top-k mask, jax.lax.top_k tie semantics.
// 2-stage 2048-bin histogram select (bits [30:20], then [19:9]) + exact
// pairwise rank on the few prefix-colliding candidates (full value desc,
// index asc — jax's tie order). pang < 2 so bit31=0 and bin1 < 2048.
// ---------------------------------------------------------------------------
__global__ void __launch_bounds__(256)
topk_mask(const float* __restrict__ adj, const float* __restrict__ noise,
          const int* __restrict__ kptr, float* __restrict__ out, int N, int kdef)
{
    __shared__ float sadj[NN];                  // 32 KB
    __shared__ unsigned hist[2048];             // 8 KB
    __shared__ unsigned tsum[256];              // 1 KB
    __shared__ unsigned segbase[32];
    __shared__ unsigned long long cand[512];    // 4 KB
    __shared__ int cand_n;
    __shared__ int s_bin, s_cgt;

    const int row = blockIdx.x;
    const int tid = threadIdx.x;
    const float* ar = adj   + (size_t)row * N;
    const float* nr = noise + (size_t)row * N;

    unsigned pbits[32];
    #pragma unroll
    for (int e = 0; e < 32; ++e) {
        const int j = tid + (e << 8);
        const float a = ar[j];
        const float p = fabsf(__fmaf_rn(0.01f, nr[j], a));
        sadj[j]  = a;
        pbits[e] = __float_as_uint(p);
    }
    if (tid == 0) cand_n = 0;

    const int k = kptr ? *kptr : kdef;

    // ===== stage 1: bins = bits [30:20] =====
    #pragma unroll
    for (int b = 0; b < 8; ++b) hist[tid * 8 + b] = 0;
    __syncthreads();
    #pragma unroll
    for (int e = 0; e < 32; ++e) atomicAdd(&hist[pbits[e] >> 20], 1u);
    __syncthreads();

    // descending suffix-scan; find bin with cnt_gt < k <= cnt_gt + hist[bin]
    {
        unsigned loc = 0;
        #pragma unroll
        for (int b = 0; b < 8; ++b) loc += hist[tid * 8 + b];
        tsum[tid] = loc;
        __syncthreads();
        if (tid < 32) {
            unsigned s = 0;
            #pragma unroll
            for (int q = 0; q < 8; ++q) s += tsum[tid * 8 + q];
            unsigned suf = s;
            #pragma unroll
            for (int o = 1; o < 32; o <<= 1) {
                const unsigned vv = __shfl_down_sync(0xffffffffu, suf, o);
                if (tid + o < 32) suf += vv;
            }
            segbase[tid] = suf - s;        // elements in higher 8-thread segments
        }
        __syncthreads();
        unsigned excl = segbase[tid >> 3];
        const int seg0 = tid & ~7;
        for (int t2 = seg0; t2 < seg0 + 8; ++t2) if (t2 > tid) excl += tsum[t2];
        unsigned cg = excl;
        for (int b = 7; b >= 0; --b) {
            const int bin = tid * 8 + b;
            const unsigned h = hist[bin];
            if (cg < (unsigned)k && (unsigned)k <= cg + h) { s_bin = bin; s_cgt = (int)cg; }
            cg += h;
        }
        __syncthreads();
    }
    const unsigned b1 = (unsigned)s_bin;
    const int kk1 = k - s_cgt;

    // ===== stage 2: bins = bits [19:9], among bucket-b1 elements =====
    #pragma unroll
    for (int b = 0; b < 8; ++b) hist[tid * 8 + b] = 0;
    __syncthreads();
    #pragma unroll
    for (int e = 0; e < 32; ++e)
        if ((pbits[e] >> 20) == b1) atomicAdd(&hist[(pbits[e] >> 9) & 0x7FF], 1u);
    __syncthreads();

    {
        unsigned loc = 0;
        #pragma unroll
        for (int b = 0; b < 8; ++b) loc += hist[tid * 8 + b];
        tsum[tid] = loc;
        __syncthreads();
        if (tid < 32) {
            unsigned s = 0;
            #pragma unroll
            for (int q = 0; q < 8; ++q) s += tsum[tid * 8 + q];
            unsigned suf = s;
            #pragma unroll
            for (int o = 1; o < 32; o <<= 1) {
                const unsigned vv = __shfl_down_sync(0xffffffffu, suf, o);
                if (tid + o < 32) suf += vv;
            }
            segbase[tid] = suf - s;
        }
        __syncthreads();
        unsigned excl = segbase[tid >> 3];
        const int seg0 = tid & ~7;
        for (int t2 = seg0; t2 < seg0 + 8; ++t2) if (t2 > tid) excl += tsum[t2];
        unsigned cg = excl;
        for (int b = 7; b >= 0; --b) {
            const int bin = tid * 8 + b;
            const unsigned h = hist[bin];
            if (cg < (unsigned)kk1 && (unsigned)kk1 <= cg + h) { s_bin = bin; s_cgt = (int)cg; }
            cg += h;
        }
        __syncthreads();
    }
    const unsigned b2 = (unsigned)s_bin;
    const int kk2 = kk1 - s_cgt;

    // ===== candidates: both prefixes match =====
    #pragma unroll
    for (int e = 0; e < 32; ++e) {
        if ((pbits[e] >> 20) == b1 && ((pbits[e] >> 9) & 0x7FF) == b2) {
            const int s = atomicAdd(&cand_n, 1);
            if (s < 512)
                cand[s] = ((unsigned long long)pbits[e] << 32)
                        | (unsigned)(tid + (e << 8));
        }
    }
    __syncthreads();
    const int cn = (cand_n < 512) ? cand_n : 512;

    // ===== final masked write =====
    #pragma unroll
    for (int e = 0; e < 32; ++e) {
        const int j = tid + (e << 8);
        bool keep = false;
        const unsigned v1 = pbits[e] >> 20;
        if (v1 > b1) keep = true;
        else if (v1 == b1) {
            const unsigned v2 = (pbits[e] >> 9) & 0x7FF;
            if (v2 > b2) keep = true;
            else if (v2 == b2) {
                int r = 0;
                for (int q = 0; q < cn; ++q) {
                    const unsigned long long c = cand[q];
                    const unsigned cv = (unsigned)(c >> 32);
                    const unsigned ci = (unsigned)c;
                    if (cv > pbits[e] || (cv == pbits[e] && ci < (unsigned)j)) ++r;
                }
                keep = (r < kk2);
            }
        }
        out[(size_t)row * N + j] = keep ? sadj[j] : 0.0f;
    }
}

// ---------------------------------------------------------------------------
// Launcher: inputs in metadata order:
// idx, emb1, emb2, lin1_w, lin1_b, lin2_w, lin2_b, noise, k
// ---------------------------------------------------------------------------
extern "C" void kernel_launch(void* const* d_in, const int* in_sizes, int n_in,
                              void* d_out, int out_size)
{
    const int*   idx   = (const int*)  d_in[0];
    const float* emb1  = (const float*)d_in[1];
    const float* emb2  = (const float*)d_in[2];
    const float* w1    = (const float*)d_in[3];
    const float* b1    = (const float*)d_in[4];
    const float* w2    = (const float*)d_in[5];
    const float* b2    = (const float*)d_in[6];
    const float* noise = (const float*)d_in[7];
    const int*   kptr  = (n_in > 8) ? (const int*)d_in[8] : nullptr;
    float* out = (float*)d_out;

    float *n1, *n2, *S;
    cudaGetSymbolAddress((void**)&n1, g_n1);
    cudaGetSymbolAddress((void**)&n2, g_n2);
    cudaGetSymbolAddress((void**)&S,  g_S);

    // Phase 1 (x2): n1/n2 = tanh(3*(emb[idx] @ W^T + b))
    {
        dim3 grid(DIMK / 128, NN / 128);
        sgemm_nt_x2_epi<<<grid, 256>>>(emb1, w1, b1, idx, n1, NN, DIMK, DIMK);
        sgemm_nt_x2_epi<<<grid, 256>>>(emb2, w2, b2, idx, n2, NN, DIMK, DIMK);
    }

    // Phase 2+3 fused: adj = tanh(3*(n1@n2^T - n2@n1^T)) directly into S
    {
        dim3 grid(NN / 128, NN / 128);
        antisym_gemm<<<grid, 512>>>(n1, n2, S, NN, DIMK);
    }

    // Phase 4: histogram-based exact top-k mask (jax tie semantics)
    topk_mask<<<NN, 256>>>(S, noise, kptr, out, NN, 64);
}

// round 12
// speedup vs baseline: 1.3699x; 1.0619x over previous
#include <cuda_runtime.h>
#include <math.h>

#define NN   8192
#define DIMK 512

// Scratch (static __device__ — allocation-free per harness rules)
__device__ float g_n1[NN * DIMK];
__device__ float g_n2[NN * DIMK];
__device__ float g_S[(size_t)NN * NN];

// ---------------------------------------------------------------------------
// Bit-exact replica of XLA's f32 tanh as actually codegen'd (FMA-contracted
// Horner chains; separate roundings for x2, x*P and the division).
// Bitwise ODD — tanh_xla(-x) == -tanh_xla(x) — relied on by the mirror write.
// ---------------------------------------------------------------------------
__device__ __forceinline__ float tanh_xla(float x)
{
    const float ax = fabsf(x);
    const float xc = fminf(fmaxf(x, -9.0f), 9.0f);
    const float x2 = __fmul_rn(xc, xc);

    float p = -2.76076847742355e-16f;
    p = __fmaf_rn(p, x2,  2.00018790482477e-13f);
    p = __fmaf_rn(p, x2, -8.60467152213735e-11f);
    p = __fmaf_rn(p, x2,  5.12229709037114e-08f);
    p = __fmaf_rn(p, x2,  1.48572235717979e-05f);
    p = __fmaf_rn(p, x2,  6.37261928875436e-04f);
    p = __fmaf_rn(p, x2,  4.89352455891786e-03f);
    const float num = __fmul_rn(xc, p);

    float q = 1.19825839466702e-06f;
    q = __fmaf_rn(q, x2, 1.18534705686654e-04f);
    q = __fmaf_rn(q, x2, 2.26843463243900e-03f);
    q = __fmaf_rn(q, x2, 4.89352518554385e-03f);

    const float r = __fdiv_rn(num, q);
    return (ax < 0.0004f) ? x : r;
}

// packed f32x2 FMA: each half is an independent rn-rounded FMA (bitwise equal
// to scalar fmaf); accumulate in place.
__device__ __forceinline__ void fma2(unsigned long long& acc,
                                     unsigned long long a2,
                                     unsigned long long b2)
{
    asm("fma.rn.f32x2 %0, %1, %2, %0;" : "+l"(acc) : "l"(a2), "l"(b2));
}

// ---------------------------------------------------------------------------
// PHASE 1: SGEMM NT x2 with gather + tanh epilogue (R6-measured best).
// ---------------------------------------------------------------------------
__global__ void __launch_bounds__(256)
sgemm_nt_x2_epi(const float* __restrict__ A, const float* __restrict__ B,
                const float* __restrict__ bias, const int* __restrict__ idx,
                float* __restrict__ C, int M, int N, int K)
{
    constexpr int BM = 128, BN = 128, BK = 16;
    __shared__ float2 As2[2][BK][BM];
    __shared__ float  Bs [2][BK][BN];

    const int tid = threadIdx.x;
    const int bx = blockIdx.x, by = blockIdx.y;

    const int lr = tid >> 2;
    const int lc = (tid & 3) << 2;

    int ar0 = idx[by * BM + lr];
    int ar1 = idx[by * BM + lr + 64];
    const float* Ap0 = A + (size_t)ar0 * K + lc;
    const float* Ap1 = A + (size_t)ar1 * K + lc;
    const float* Bp0 = B + (size_t)(bx * BN + lr) * K + lc;
    const float* Bp1 = B + (size_t)(bx * BN + lr + 64) * K + lc;

    const int rm = (tid >> 4) << 3;
    const int rn = (tid & 15) << 3;

    unsigned long long acc2[8][4];
    #pragma unroll
    for (int i = 0; i < 8; ++i)
        #pragma unroll
        for (int j = 0; j < 4; ++j) acc2[i][j] = 0ull;

    float4 pa0, pa1, pb0, pb1;

    pa0 = *reinterpret_cast<const float4*>(Ap0);
    pa1 = *reinterpret_cast<const float4*>(Ap1);
    pb0 = *reinterpret_cast<const float4*>(Bp0);
    pb1 = *reinterpret_cast<const float4*>(Bp1);
    {
        As2[0][lc + 0][lr] = make_float2(pa0.x, pa0.x);
        As2[0][lc + 1][lr] = make_float2(pa0.y, pa0.y);
        As2[0][lc + 2][lr] = make_float2(pa0.z, pa0.z);
        As2[0][lc + 3][lr] = make_float2(pa0.w, pa0.w);
        As2[0][lc + 0][lr + 64] = make_float2(pa1.x, pa1.x);
        As2[0][lc + 1][lr + 64] = make_float2(pa1.y, pa1.y);
        As2[0][lc + 2][lr + 64] = make_float2(pa1.z, pa1.z);
        As2[0][lc + 3][lr + 64] = make_float2(pa1.w, pa1.w);
        Bs[0][lc + 0][lr] = pb0.x; Bs[0][lc + 1][lr] = pb0.y;
        Bs[0][lc + 2][lr] = pb0.z; Bs[0][lc + 3][lr] = pb0.w;
        Bs[0][lc + 0][lr + 64] = pb1.x; Bs[0][lc + 1][lr + 64] = pb1.y;
        Bs[0][lc + 2][lr + 64] = pb1.z; Bs[0][lc + 3][lr + 64] = pb1.w;
    }
    __syncthreads();

    int read = 0;
    for (int kt = BK; kt <= K; kt += BK) {
        const bool more = (kt < K);
        if (more) {
            pa0 = *reinterpret_cast<const float4*>(Ap0 + kt);
            pa1 = *reinterpret_cast<const float4*>(Ap1 + kt);
            pb0 = *reinterpret_cast<const float4*>(Bp0 + kt);
            pb1 = *reinterpret_cast<const float4*>(Bp1 + kt);
        }
        #pragma unroll
        for (int kk = 0; kk < BK; ++kk) {
            unsigned long long ra2[8], rb2[4];
            *reinterpret_cast<float4*>(&ra2[0]) = *reinterpret_cast<const float4*>(&As2[read][kk][rm]);
            *reinterpret_cast<float4*>(&ra2[2]) = *reinterpret_cast<const float4*>(&As2[read][kk][rm + 2]);
            *reinterpret_cast<float4*>(&ra2[4]) = *reinterpret_cast<const float4*>(&As2[read][kk][rm + 4]);
            *reinterpret_cast<float4*>(&ra2[6]) = *reinterpret_cast<const float4*>(&As2[read][kk][rm + 6]);
            *reinterpret_cast<float4*>(&rb2[0]) = *reinterpret_cast<const float4*>(&Bs[read][kk][rn]);
            *reinterpret_cast<float4*>(&rb2[2]) = *reinterpret_cast<const float4*>(&Bs[read][kk][rn + 4]);

            #pragma unroll
            for (int i = 0; i < 8; ++i)
                #pragma unroll
                for (int j = 0; j < 4; ++j)
                    fma2(acc2[i][j], ra2[i], rb2[j]);
        }
        if (more) {
            const int w = read ^ 1;
            As2[w][lc + 0][lr] = make_float2(pa0.x, pa0.x);
            As2[w][lc + 1][lr] = make_float2(pa0.y, pa0.y);
            As2[w][lc + 2][lr] = make_float2(pa0.z, pa0.z);
            As2[w][lc + 3][lr] = make_float2(pa0.w, pa0.w);
            As2[w][lc + 0][lr + 64] = make_float2(pa1.x, pa1.x);
            As2[w][lc + 1][lr + 64] = make_float2(pa1.y, pa1.y);
            As2[w][lc + 2][lr + 64] = make_float2(pa1.z, pa1.z);
            As2[w][lc + 3][lr + 64] = make_float2(pa1.w, pa1.w);
            Bs[w][lc + 0][lr] = pb0.x; Bs[w][lc + 1][lr] = pb0.y;
            Bs[w][lc + 2][lr] = pb0.z; Bs[w][lc + 3][lr] = pb0.w;
            Bs[w][lc + 0][lr + 64] = pb1.x; Bs[w][lc + 1][lr + 64] = pb1.y;
            Bs[w][lc + 2][lr + 64] = pb1.z; Bs[w][lc + 3][lr + 64] = pb1.w;
            __syncthreads();
            read = w;
        }
    }

    #pragma unroll
    for (int i = 0; i < 8; ++i) {
        const size_t row = (size_t)(by * BM + rm + i);
        float v[8];
        #pragma unroll
        for (int j = 0; j < 4; ++j) {
            const float2 u = *reinterpret_cast<const float2*>(&acc2[i][j]);
            v[2 * j]     = u.x;
            v[2 * j + 1] = u.y;
        }
        #pragma unroll
        for (int j = 0; j < 8; ++j) {
            float x = __fadd_rn(v[j], bias[bx * BN + rn + j]);
            x = __fmul_rn(3.0f, x);
            v[j] = tanh_xla(x);
        }
        float4* cp = reinterpret_cast<float4*>(C + row * (size_t)N + bx * BN + rn);
        cp[0] = make_float4(v[0], v[1], v[2], v[3]);
        cp[1] = make_float4(v[4], v[5], v[6], v[7]);
    }
}

// ---------------------------------------------------------------------------
// PHASE 2+3 FUSED: adj = tanh(3*(n1@n2^T - n2@n1^T)) written directly.
// (R10-measured ~1615us — at the scalar FFMA roofline.)
// ---------------------------------------------------------------------------
__global__ void __launch_bounds__(512, 1)
antisym_gemm(const float* __restrict__ n1, const float* __restrict__ n2,
             float* __restrict__ adj, int N, int K)
{
    const int I = blockIdx.y, J = blockIdx.x;
    if (J < I) return;

    constexpr int BK = 16;
    __shared__ float As1[2][BK][132];
    __shared__ float As2[2][BK][132];
    __shared__ float Bs1[2][BK][132];
    __shared__ float Bs2[2][BK][132];

    const int tid = threadIdx.x;

    const int which = tid >> 7;
    const int t4 = tid & 127;
    const int lr = t4 >> 2;
    const int lc = (t4 & 3) << 2;

    const float* src;
    int rowbase;
    if (which == 0)      { src = n1; rowbase = I * 128; }
    else if (which == 1) { src = n2; rowbase = I * 128; }
    else if (which == 2) { src = n2; rowbase = J * 128; }
    else                 { src = n1; rowbase = J * 128; }
    const float* lp = src + (size_t)(rowbase + lr) * K + lc;

    float (*dst)[BK][132] = (which == 0) ? As1 : (which == 1) ? As2
                          : (which == 2) ? Bs1 : Bs2;

    const int rm = (tid >> 5) << 3;
    const int rn = (tid & 31) << 2;

    float acc1[8][4], acc2[8][4];
    #pragma unroll
    for (int i = 0; i < 8; ++i)
        #pragma unroll
        for (int j = 0; j < 4; ++j) { acc1[i][j] = 0.0f; acc2[i][j] = 0.0f; }

    float4 pf[4];

    #pragma unroll
    for (int r = 0; r < 4; ++r)
        pf[r] = *reinterpret_cast<const float4*>(lp + (size_t)(r * 32) * K);
    #pragma unroll
    for (int r = 0; r < 4; ++r) {
        const int row = lr + r * 32;
        dst[0][lc + 0][row] = pf[r].x;
        dst[0][lc + 1][row] = pf[r].y;
        dst[0][lc + 2][row] = pf[r].z;
        dst[0][lc + 3][row] = pf[r].w;
    }
    __syncthreads();

    int read = 0;
    for (int kt = BK; kt <= K; kt += BK) {
        const bool more = (kt < K);
        if (more) {
            #pragma unroll
            for (int r = 0; r < 4; ++r)
                pf[r] = *reinterpret_cast<const float4*>(lp + (size_t)(r * 32) * K + kt);
        }
        #pragma unroll
        for (int kk = 0; kk < BK; ++kk) {
            float ra1[8], ra2[8], rb1[4], rb2[4];
            *reinterpret_cast<float4*>(&ra1[0]) = *reinterpret_cast<const float4*>(&As1[read][kk][rm]);
            *reinterpret_cast<float4*>(&ra1[4]) = *reinterpret_cast<const float4*>(&As1[read][kk][rm + 4]);
            *reinterpret_cast<float4*>(&ra2[0]) = *reinterpret_cast<const float4*>(&As2[read][kk][rm]);
            *reinterpret_cast<float4*>(&ra2[4]) = *reinterpret_cast<const float4*>(&As2[read][kk][rm + 4]);
            *reinterpret_cast<float4*>(&rb1[0]) = *reinterpret_cast<const float4*>(&Bs1[read][kk][rn]);
            *reinterpret_cast<float4*>(&rb2[0]) = *reinterpret_cast<const float4*>(&Bs2[read][kk][rn]);

            #pragma unroll
            for (int i = 0; i < 8; ++i)
                #pragma unroll
                for (int j = 0; j < 4; ++j)
                    acc1[i][j] = fmaf(ra1[i], rb1[j], acc1[i][j]);
            #pragma unroll
            for (int i = 0; i < 8; ++i)
                #pragma unroll
                for (int j = 0; j < 4; ++j)
                    acc2[i][j] = fmaf(ra2[i], rb2[j], acc2[i][j]);
        }
        if (more) {
            const int w = read ^ 1;
            #pragma unroll
            for (int r = 0; r < 4; ++r) {
                const int row = lr + r * 32;
                dst[w][lc + 0][row] = pf[r].x;
                dst[w][lc + 1][row] = pf[r].y;
                dst[w][lc + 2][row] = pf[r].z;
                dst[w][lc + 3][row] = pf[r].w;
            }
            __syncthreads();
            read = w;
        }
    }

    float v[8][4];
    #pragma unroll
    for (int i = 0; i < 8; ++i)
        #pragma unroll
        for (int j = 0; j < 4; ++j) {
            const float a = __fadd_rn(acc1[i][j], -acc2[i][j]);
            v[i][j] = tanh_xla(__fmul_rn(3.0f, a));
        }

    #pragma unroll
    for (int i = 0; i < 8; ++i) {
        float4* cp = reinterpret_cast<float4*>(
            adj + (size_t)(I * 128 + rm + i) * N + J * 128 + rn);
        *cp = make_float4(v[i][0], v[i][1], v[i][2], v[i][3]);
    }

    if (I != J) {
        #pragma unroll
        for (int j = 0; j < 4; ++j) {
            float4* mp = reinterpret_cast<float4*>(
                adj + (size_t)(J * 128 + rn + j) * N + I * 128 + rm);
            mp[0] = make_float4(-v[0][j], -v[1][j], -v[2][j], -v[3][j]);
            mp[1] = make_float4(-v[4][j], -v[5][j], -v[6][j], -v[7][j]);
        }
    }
}

// ---------------------------------------------------------------------------
// PHASE 4: per-row exact top-k mask, jax.lax.top_k tie semantics.
// Occupancy-first rebuild: 512 threads x 16 elems, pbits in regs (16/thread),
// NO adj staging (final write re-reads adj from global — DRAM had 4x headroom,
// occupancy was 8 warps/SM and is the binding constraint).
// 2-stage 2048-bin histogram select (bits [30:20], then [19:9]) + exact
// pairwise tie rank (value desc, index asc). pang < 2 so bit31=0.
// ---------------------------------------------------------------------------
__global__ void __launch_bounds__(512)
topk_mask(const float* __restrict__ adj, const float* __restrict__ noise,
          const int* __restrict__ kptr, float* __restrict__ out, int N, int kdef)
{
    __shared__ unsigned hist[2048];             // 8 KB
    __shared__ unsigned tsum[512];              // 2 KB
    __shared__ unsigned segbase[32];
    __shared__ unsigned long long cand[512];    // 4 KB
    __shared__ int cand_n;
    __shared__ int s_bin, s_cgt;

    const int row = blockIdx.x;
    const int tid = threadIdx.x;
    const float* ar = adj   + (size_t)row * N;
    const float* nr = noise + (size_t)row * N;

    unsigned pbits[16];
    #pragma unroll
    for (int e = 0; e < 16; ++e) {
        const int j = tid + (e << 9);
        const float a = ar[j];
        const float p = fabsf(__fmaf_rn(0.01f, nr[j], a));
        pbits[e] = __float_as_uint(p);
    }
    if (tid == 0) cand_n = 0;

    const int k = kptr ? *kptr : kdef;

    // ===== stage 1: bins = bits [30:20] =====
    #pragma unroll
    for (int b = 0; b < 4; ++b) hist[tid * 4 + b] = 0;
    __syncthreads();
    #pragma unroll
    for (int e = 0; e < 16; ++e) atomicAdd(&hist[pbits[e] >> 20], 1u);
    __syncthreads();

    // descending suffix-scan over 2048 bins (4 bins/thread, 16-thread segs x32)
    {
        unsigned loc = hist[tid * 4] + hist[tid * 4 + 1]
                     + hist[tid * 4 + 2] + hist[tid * 4 + 3];
        tsum[tid] = loc;
        __syncthreads();
        if (tid < 32) {
            unsigned s = 0;
            #pragma unroll
            for (int q = 0; q < 16; ++q) s += tsum[tid * 16 + q];
            unsigned suf = s;
            #pragma unroll
            for (int o = 1; o < 32; o <<= 1) {
                const unsigned vv = __shfl_down_sync(0xffffffffu, suf, o);
                if (tid + o < 32) suf += vv;
            }
            segbase[tid] = suf - s;        // elements in strictly-higher segments
        }
        __syncthreads();
        unsigned excl = segbase[tid >> 4];
        const int seg0 = tid & ~15;
        for (int t2 = seg0; t2 < seg0 + 16; ++t2) if (t2 > tid) excl += tsum[t2];
        unsigned cg = excl;
        for (int b = 3; b >= 0; --b) {
            const int bin = tid * 4 + b;
            const unsigned h = hist[bin];
            if (cg < (unsigned)k && (unsigned)k <= cg + h) { s_bin = bin; s_cgt = (int)cg; }
            cg += h;
        }
        __syncthreads();
    }
    const unsigned b1 = (unsigned)s_bin;
    const int kk1 = k - s_cgt;

    // ===== stage 2: bins = bits [19:9], among bucket-b1 elements =====
    #pragma unroll
    for (int b = 0; b < 4; ++b) hist[tid * 4 + b] = 0;
    __syncthreads();
    #pragma unroll
    for (int e = 0; e < 16; ++e)
        if ((pbits[e] >> 20) == b1) atomicAdd(&hist[(pbits[e] >> 9) & 0x7FF], 1u);
    __syncthreads();

    {
        unsigned loc = hist[tid * 4] + hist[tid * 4 + 1]
                     + hist[tid * 4 + 2] + hist[tid * 4 + 3];
        tsum[tid] = loc;
        __syncthreads();
        if (tid < 32) {
            unsigned s = 0;
            #pragma unroll
            for (int q = 0; q < 16; ++q) s += tsum[tid * 16 + q];
            unsigned suf = s;
            #pragma unroll
            for (int o = 1; o < 32; o <<= 1) {
                const unsigned vv = __shfl_down_sync(0xffffffffu, suf, o);
                if (tid + o < 32) suf += vv;
            }
            segbase[tid] = suf - s;
        }
        __syncthreads();
        unsigned excl = segbase[tid >> 4];
        const int seg0 = tid & ~15;
        for (int t2 = seg0; t2 < seg0 + 16; ++t2) if (t2 > tid) excl += tsum[t2];
        unsigned cg = excl;
        for (int b = 3; b >= 0; --b) {
            const int bin = tid * 4 + b;
            const unsigned h = hist[bin];
            if (cg < (unsigned)kk1 && (unsigned)kk1 <= cg + h) { s_bin = bin; s_cgt = (int)cg; }
            cg += h;
        }
        __syncthreads();
    }
    const unsigned b2 = (unsigned)s_bin;
    const int kk2 = kk1 - s_cgt;

    // ===== candidates: both prefixes match =====
    #pragma unroll
    for (int e = 0; e < 16; ++e) {
        if ((pbits[e] >> 20) == b1 && ((pbits[e] >> 9) & 0x7FF) == b2) {
            const int s = atomicAdd(&cand_n, 1);
            if (s < 512)
                cand[s] = ((unsigned long long)pbits[e] << 32)
                        | (unsigned)(tid + (e << 9));
        }
    }
    __syncthreads();
    const int cn = (cand_n < 512) ? cand_n : 512;

    // ===== final masked write (re-read adj from global) =====
    #pragma unroll
    for (int e = 0; e < 16; ++e) {
        const int j = tid + (e << 9);
        bool keep = false;
        const unsigned v1 = pbits[e] >> 20;
        if (v1 > b1) keep = true;
        else if (v1 == b1) {
            const unsigned v2 = (pbits[e] >> 9) & 0x7FF;
            if (v2 > b2) keep = true;
            else if (v2 == b2) {
                int r = 0;
                for (int q = 0; q < cn; ++q) {
                    const unsigned long long c = cand[q];
                    const unsigned cv = (unsigned)(c >> 32);
                    const unsigned ci = (unsigned)c;
                    if (cv > pbits[e] || (cv == pbits[e] && ci < (unsigned)j)) ++r;
                }
                keep = (r < kk2);
            }
        }
        out[(size_t)row * N + j] = keep ? ar[j] : 0.0f;
    }
}

// ---------------------------------------------------------------------------
// Launcher: inputs in metadata order:
// idx, emb1, emb2, lin1_w, lin1_b, lin2_w, lin2_b, noise, k
// ---------------------------------------------------------------------------
extern "C" void kernel_launch(void* const* d_in, const int* in_sizes, int n_in,
                              void* d_out, int out_size)
{
    const int*   idx   = (const int*)  d_in[0];
    const float* emb1  = (const float*)d_in[1];
    const float* emb2  = (const float*)d_in[2];
    const float* w1    = (const float*)d_in[3];
    const float* b1    = (const float*)d_in[4];
    const float* w2    = (const float*)d_in[5];
    const float* b2    = (const float*)d_in[6];
    const float* noise = (const float*)d_in[7];
    const int*   kptr  = (n_in > 8) ? (const int*)d_in[8] : nullptr;
    float* out = (float*)d_out;

    float *n1, *n2, *S;
    cudaGetSymbolAddress((void**)&n1, g_n1);
    cudaGetSymbolAddress((void**)&n2, g_n2);
    cudaGetSymbolAddress((void**)&S,  g_S);

    // Phase 1 (x2): n1/n2 = tanh(3*(emb[idx] @ W^T + b))
    {
        dim3 grid(DIMK / 128, NN / 128);
        sgemm_nt_x2_epi<<<grid, 256>>>(emb1, w1, b1, idx, n1, NN, DIMK, DIMK);
        sgemm_nt_x2_epi<<<grid, 256>>>(emb2, w2, b2, idx, n2, NN, DIMK, DIMK);
    }

    // Phase 2+3 fused: adj = tanh(3*(n1@n2^T - n2@n1^T)) directly into S
    {
        dim3 grid(NN / 128, NN / 128);
        antisym_gemm<<<grid, 512>>>(n1, n2, S, NN, DIMK);
    }

    // Phase 4: occupancy-first histogram top-k mask (jax tie semantics)
    topk_mask<<<NN, 512>>>(S, noise, kptr, out, NN, 64);
}